// round 1
// baseline (speedup 1.0000x reference)
#include <cuda_runtime.h>
#include <cstdint>

#define D 128
#define NE 500000
#define NGRID 200000
#define NMESH 40000
#define LNEPS 1e-5f

// Scratch for scatter-add aggregation (allocation-free rule: __device__ global).
__device__ __align__(16) float g_agg[(size_t)NMESH * D];

__global__ void zero_agg_kernel() {
    size_t i = (size_t)blockIdx.x * blockDim.x + threadIdx.x;
    if (i < (size_t)NMESH * D / 4) {
        ((float4*)g_agg)[i] = make_float4(0.f, 0.f, 0.f, 0.f);
    }
}

__device__ __forceinline__ float silu_f(float x) {
    return x / (1.0f + __expf(-x));
}

// Fused MLP: y = LN(silu(cat @ w1 + b1) @ w2 + b2) * g + b  [+ resid / scatter-add]
// Block tile: 128 rows x 128 cols. 256 threads, 8x8 micro-tile each.
// MODE: 0 = edge (scatter-add to g_agg via scat idx)
//       1 = dst/mesh (seg0 = g_agg, seg1 = mesh, residual out)
//       2 = src/grid (seg0 = grid, residual out)
template<int NSEG, int MODE>
__global__ __launch_bounds__(256, 2)
void mlp_kernel(const float* __restrict__ seg0,
                const float* __restrict__ seg1,
                const float* __restrict__ seg2,
                const int* __restrict__ idx1,
                const int* __restrict__ idx2,
                int M,
                const float* __restrict__ w1, const float* __restrict__ b1,
                const float* __restrict__ w2, const float* __restrict__ b2,
                const float* __restrict__ gam, const float* __restrict__ bet,
                const float* __restrict__ resid,
                float* __restrict__ outp,
                const int* __restrict__ scat)
{
    extern __shared__ float smem[];
    float* As = smem;             // [8][128]  A chunk, k-major
    float* Bs = As + 8 * 128;     // [8][128]  B chunk
    float* Hs = Bs + 8 * 128;     // [128][132] hidden (k-major), reused for y (m-major)
    const float** RP = (const float**)(Hs + 132 * 128);  // row pointers per segment

    const int t  = threadIdx.x;
    const int tx = t & 15;
    const int ty = t >> 4;
    const int m0 = blockIdx.x * 128;

    const float* s0 = (MODE == 1) ? (const float*)g_agg : seg0;

    // Precompute gathered row pointers (clamped for tail blocks)
    for (int r = t; r < 128; r += 256) {
        int m = min(m0 + r, M - 1);
        RP[r] = s0 + (size_t)m * D;
        if (NSEG >= 2) RP[128 + r] = seg1 + (size_t)((MODE == 0) ? idx1[m] : m) * D;
        if (NSEG >= 3) RP[256 + r] = seg2 + (size_t)idx2[m] * D;
    }
    __syncthreads();

    float acc[8][8];
#pragma unroll
    for (int i = 0; i < 8; ++i)
#pragma unroll
        for (int j = 0; j < 8; ++j) acc[i][j] = 0.f;

    // ---------------- GEMM1: cat[128 x NSEG*128] @ w1 ----------------
    const int K1 = NSEG * D;
    for (int kc = 0; kc < K1; kc += 8) {
        {   // stage A (gathered), transpose to k-major
            const int r = t >> 1;
            const int c = (t & 1) * 4;
            const float* p = RP[(kc >> 7) * 128 + r] + (kc & 127) + c;
            float4 v = *(const float4*)p;
            As[(c + 0) * 128 + r] = v.x;
            As[(c + 1) * 128 + r] = v.y;
            As[(c + 2) * 128 + r] = v.z;
            As[(c + 3) * 128 + r] = v.w;
        }
        {   // stage B from w1
            const int kk = t >> 5;
            const int n = (t & 31) * 4;
            *(float4*)(Bs + kk * 128 + n) = *(const float4*)(w1 + (size_t)(kc + kk) * D + n);
        }
        __syncthreads();
#pragma unroll
        for (int k = 0; k < 8; ++k) {
            float4 a0  = *(const float4*)(As + k * 128 + ty * 4);
            float4 a1  = *(const float4*)(As + k * 128 + 64 + ty * 4);
            float4 bv0 = *(const float4*)(Bs + k * 128 + tx * 4);
            float4 bv1 = *(const float4*)(Bs + k * 128 + 64 + tx * 4);
            float av[8] = {a0.x, a0.y, a0.z, a0.w, a1.x, a1.y, a1.z, a1.w};
            float bw[8] = {bv0.x, bv0.y, bv0.z, bv0.w, bv1.x, bv1.y, bv1.z, bv1.w};
#pragma unroll
            for (int i = 0; i < 8; ++i)
#pragma unroll
                for (int j = 0; j < 8; ++j)
                    acc[i][j] = fmaf(av[i], bw[j], acc[i][j]);
        }
        __syncthreads();
    }

    // bias + SiLU, store hidden TRANSPOSED (k-major) so GEMM2 reads it as A directly
    {
        float bias1[8];
        float4 u0 = *(const float4*)(b1 + tx * 4);
        float4 u1 = *(const float4*)(b1 + 64 + tx * 4);
        bias1[0] = u0.x; bias1[1] = u0.y; bias1[2] = u0.z; bias1[3] = u0.w;
        bias1[4] = u1.x; bias1[5] = u1.y; bias1[6] = u1.z; bias1[7] = u1.w;
#pragma unroll
        for (int j = 0; j < 8; ++j) {
            int n = (j < 4) ? (tx * 4 + j) : (64 + tx * 4 + (j - 4));
            float4 v0, v1;
            v0.x = silu_f(acc[0][j] + bias1[j]);
            v0.y = silu_f(acc[1][j] + bias1[j]);
            v0.z = silu_f(acc[2][j] + bias1[j]);
            v0.w = silu_f(acc[3][j] + bias1[j]);
            v1.x = silu_f(acc[4][j] + bias1[j]);
            v1.y = silu_f(acc[5][j] + bias1[j]);
            v1.z = silu_f(acc[6][j] + bias1[j]);
            v1.w = silu_f(acc[7][j] + bias1[j]);
            *(float4*)(Hs + n * 132 + ty * 4)      = v0;
            *(float4*)(Hs + n * 132 + 64 + ty * 4) = v1;
        }
    }
    __syncthreads();

    // ---------------- GEMM2: h[128x128] @ w2 ----------------
#pragma unroll
    for (int i = 0; i < 8; ++i)
#pragma unroll
        for (int j = 0; j < 8; ++j) acc[i][j] = 0.f;

    for (int kc = 0; kc < D; kc += 8) {
        {   // stage B from w2
            const int kk = t >> 5;
            const int n = (t & 31) * 4;
            *(float4*)(Bs + kk * 128 + n) = *(const float4*)(w2 + (size_t)(kc + kk) * D + n);
        }
        __syncthreads();
#pragma unroll
        for (int k = 0; k < 8; ++k) {
            float4 a0  = *(const float4*)(Hs + (kc + k) * 132 + ty * 4);
            float4 a1  = *(const float4*)(Hs + (kc + k) * 132 + 64 + ty * 4);
            float4 bv0 = *(const float4*)(Bs + k * 128 + tx * 4);
            float4 bv1 = *(const float4*)(Bs + k * 128 + 64 + tx * 4);
            float av[8] = {a0.x, a0.y, a0.z, a0.w, a1.x, a1.y, a1.z, a1.w};
            float bw[8] = {bv0.x, bv0.y, bv0.z, bv0.w, bv1.x, bv1.y, bv1.z, bv1.w};
#pragma unroll
            for (int i = 0; i < 8; ++i)
#pragma unroll
                for (int j = 0; j < 8; ++j)
                    acc[i][j] = fmaf(av[i], bw[j], acc[i][j]);
        }
        __syncthreads();
    }

    // y = acc + b2, store m-major into Hs (all reads of h are done: synced above)
    {
        float bias2[8];
        float4 u0 = *(const float4*)(b2 + tx * 4);
        float4 u1 = *(const float4*)(b2 + 64 + tx * 4);
        bias2[0] = u0.x; bias2[1] = u0.y; bias2[2] = u0.z; bias2[3] = u0.w;
        bias2[4] = u1.x; bias2[5] = u1.y; bias2[6] = u1.z; bias2[7] = u1.w;
#pragma unroll
        for (int i = 0; i < 8; ++i) {
            int m = (i < 4) ? (ty * 4 + i) : (64 + ty * 4 + (i - 4));
            float4 v0 = make_float4(acc[i][0] + bias2[0], acc[i][1] + bias2[1],
                                    acc[i][2] + bias2[2], acc[i][3] + bias2[3]);
            float4 v1 = make_float4(acc[i][4] + bias2[4], acc[i][5] + bias2[5],
                                    acc[i][6] + bias2[6], acc[i][7] + bias2[7]);
            *(float4*)(Hs + m * 132 + tx * 4)      = v0;
            *(float4*)(Hs + m * 132 + 64 + tx * 4) = v1;
        }
    }
    __syncthreads();

    // ---------------- LayerNorm + output / scatter ----------------
    {
        const int w = t >> 5, lane = t & 31;
        float4 gm = *(const float4*)(gam + lane * 4);
        float4 bt = *(const float4*)(bet + lane * 4);
        for (int r = w; r < 128; r += 8) {
            float4 v = *(const float4*)(Hs + r * 132 + lane * 4);
            float s  = v.x + v.y + v.z + v.w;
            float ss = fmaf(v.x, v.x, fmaf(v.y, v.y, fmaf(v.z, v.z, v.w * v.w)));
#pragma unroll
            for (int off = 16; off > 0; off >>= 1) {
                s  += __shfl_xor_sync(0xffffffffu, s, off);
                ss += __shfl_xor_sync(0xffffffffu, ss, off);
            }
            float mu  = s * (1.0f / 128.0f);
            float var = ss * (1.0f / 128.0f) - mu * mu;
            float rs  = rsqrtf(var + LNEPS);
            float4 o;
            o.x = (v.x - mu) * rs * gm.x + bt.x;
            o.y = (v.y - mu) * rs * gm.y + bt.y;
            o.z = (v.z - mu) * rs * gm.z + bt.z;
            o.w = (v.w - mu) * rs * gm.w + bt.w;
            int m = m0 + r;
            if (m < M) {
                if (MODE == 0) {
                    float* p = g_agg + (size_t)scat[m] * D + lane * 4;
                    atomicAdd(p + 0, o.x);
                    atomicAdd(p + 1, o.y);
                    atomicAdd(p + 2, o.z);
                    atomicAdd(p + 3, o.w);
                } else {
                    float4 rv = *(const float4*)(resid + (size_t)m * D + lane * 4);
                    o.x += rv.x; o.y += rv.y; o.z += rv.z; o.w += rv.w;
                    *(float4*)(outp + (size_t)m * D + lane * 4) = o;
                }
            }
        }
    }
}

extern "C" void kernel_launch(void* const* d_in, const int* in_sizes, int n_in,
                              void* d_out, int out_size) {
    const float* g2m  = (const float*)d_in[0];
    const float* grid = (const float*)d_in[1];
    const float* mesh = (const float*)d_in[2];
    const int*   src  = (const int*)d_in[3];
    const int*   dst  = (const int*)d_in[4];
    const float* ew1 = (const float*)d_in[5];
    const float* eb1 = (const float*)d_in[6];
    const float* ew2 = (const float*)d_in[7];
    const float* eb2 = (const float*)d_in[8];
    const float* eg  = (const float*)d_in[9];
    const float* ebt = (const float*)d_in[10];
    const float* sw1 = (const float*)d_in[11];
    const float* sb1 = (const float*)d_in[12];
    const float* sw2 = (const float*)d_in[13];
    const float* sb2 = (const float*)d_in[14];
    const float* sg  = (const float*)d_in[15];
    const float* sbt = (const float*)d_in[16];
    const float* dw1 = (const float*)d_in[17];
    const float* db1 = (const float*)d_in[18];
    const float* dw2 = (const float*)d_in[19];
    const float* db2 = (const float*)d_in[20];
    const float* dg  = (const float*)d_in[21];
    const float* dbt = (const float*)d_in[22];

    float* grid_out = (float*)d_out;                      // [NGRID, D] first
    float* mesh_out = grid_out + (size_t)NGRID * D;       // then [NMESH, D]

    const int SMEM_BASE = (8 * 128 + 8 * 128 + 132 * 128) * 4;  // 75776 B
    const int smem3 = SMEM_BASE + 3 * 128 * 8;
    const int smem2 = SMEM_BASE + 2 * 128 * 8;
    const int smem1 = SMEM_BASE + 1 * 128 * 8;

    cudaFuncSetAttribute(mlp_kernel<3,0>, cudaFuncAttributeMaxDynamicSharedMemorySize, smem3);
    cudaFuncSetAttribute(mlp_kernel<2,1>, cudaFuncAttributeMaxDynamicSharedMemorySize, smem2);
    cudaFuncSetAttribute(mlp_kernel<1,2>, cudaFuncAttributeMaxDynamicSharedMemorySize, smem1);

    // 1) zero the aggregation scratch
    zero_agg_kernel<<<(NMESH * D / 4 + 255) / 256, 256>>>();

    // 2) edge MLP (gathered concat) + LN + scatter-add into g_agg
    mlp_kernel<3,0><<<(NE + 127) / 128, 256, smem3>>>(
        g2m, grid, mesh, src, dst, NE,
        ew1, eb1, ew2, eb2, eg, ebt, nullptr, nullptr, dst);

    // 3) grid node MLP + residual
    mlp_kernel<1,2><<<(NGRID + 127) / 128, 256, smem1>>>(
        grid, nullptr, nullptr, nullptr, nullptr, NGRID,
        sw1, sb1, sw2, sb2, sg, sbt, grid, grid_out, nullptr);

    // 4) mesh node MLP on [agg | mesh] + residual
    mlp_kernel<2,1><<<(NMESH + 127) / 128, 256, smem2>>>(
        nullptr, mesh, nullptr, nullptr, nullptr, NMESH,
        dw1, db1, dw2, db2, dg, dbt, mesh, mesh_out, nullptr);
}

// round 2
// speedup vs baseline: 3.0796x; 3.0796x over previous
#include <cuda_runtime.h>
#include <cstdint>

#define D 128
#define NE 500000
#define NGRID 200000
#define NMESH 40000
#define LNEPS 1e-5f

#define AS_STRIDE 20   // 16 k + 4 pad  -> conflict-free A-frag reads
#define BS_STRIDE 136  // 128 n + 8 pad -> conflict-free B-frag reads
#define HS_STRIDE 132  // 128 n + 4 pad
#define AS_WORDS (128 * AS_STRIDE)
#define BS_WORDS (16 * BS_STRIDE)
#define HS_WORDS (128 * HS_STRIDE)

// Scratch for scatter-add aggregation (allocation-free rule: __device__ global).
__device__ __align__(16) float g_agg[(size_t)NMESH * D];

__global__ void zero_agg_kernel() {
    size_t i = (size_t)blockIdx.x * blockDim.x + threadIdx.x;
    if (i < (size_t)NMESH * D / 4) {
        ((float4*)g_agg)[i] = make_float4(0.f, 0.f, 0.f, 0.f);
    }
}

__device__ __forceinline__ float silu_f(float x) {
    return x / (1.0f + __expf(-x));
}

__device__ __forceinline__ uint32_t f2tf(float x) {
    uint32_t r;
    asm("cvt.rna.tf32.f32 %0, %1;" : "=r"(r) : "f"(x));
    return r;
}

__device__ __forceinline__ void mma8(float* c, const uint32_t* a, const uint32_t* b) {
    asm volatile(
        "mma.sync.aligned.m16n8k8.row.col.f32.tf32.tf32.f32 "
        "{%0,%1,%2,%3}, {%4,%5,%6,%7}, {%8,%9}, {%0,%1,%2,%3};"
        : "+f"(c[0]), "+f"(c[1]), "+f"(c[2]), "+f"(c[3])
        : "r"(a[0]), "r"(a[1]), "r"(a[2]), "r"(a[3]), "r"(b[0]), "r"(b[1]));
}

// Fused MLP via tf32 mma.sync: y = LN(silu(cat @ w1 + b1) @ w2 + b2) * g + b
// Block: 128 rows x 128 cols, 256 threads = 8 warps (4 m x 2 n), warp tile 32x64.
// MODE: 0 = edge (scatter-add to g_agg), 1 = mesh (seg0 = g_agg, residual),
//       2 = grid (residual)
template<int NSEG, int MODE>
__global__ __launch_bounds__(256, 2)
void mlp_kernel(const float* __restrict__ seg0,
                const float* __restrict__ seg1,
                const float* __restrict__ seg2,
                const int* __restrict__ idx1,
                const int* __restrict__ idx2,
                int M,
                const float* __restrict__ w1, const float* __restrict__ b1,
                const float* __restrict__ w2, const float* __restrict__ b2,
                const float* __restrict__ gam, const float* __restrict__ bet,
                const float* __restrict__ resid,
                float* __restrict__ outp,
                const int* __restrict__ scat)
{
    extern __shared__ uint32_t sm_u[];
    uint32_t* As = sm_u;                       // [128][AS_STRIDE] tf32 bits
    uint32_t* Bs = As + AS_WORDS;              // [16][BS_STRIDE] tf32 bits
    float*    Hs = (float*)(Bs + BS_WORDS);    // [128][HS_STRIDE] h (tf32 bits) / y (f32)
    const float** RP = (const float**)(Hs + HS_WORDS);

    const int t    = threadIdx.x;
    const int lane = t & 31;
    const int warp = t >> 5;
    const int wm   = warp & 3;          // warp row group (32 rows)
    const int wn   = warp >> 2;         // warp col group (64 cols)
    const int g    = lane >> 2;         // mma groupID
    const int c4   = lane & 3;          // mma threadID-in-group
    const int m0   = blockIdx.x * 128;
    const int rm   = wm * 32;

    const float* s0 = (MODE == 1) ? (const float*)g_agg : seg0;

    for (int r = t; r < 128; r += 256) {
        int m = min(m0 + r, M - 1);
        RP[r] = s0 + (size_t)m * D;
        if (NSEG >= 2) RP[128 + r] = seg1 + (size_t)((MODE == 0) ? idx1[m] : m) * D;
        if (NSEG >= 3) RP[256 + r] = seg2 + (size_t)idx2[m] * D;
    }
    __syncthreads();

    float acc[2][8][4];
#pragma unroll
    for (int mt = 0; mt < 2; ++mt)
#pragma unroll
        for (int jt = 0; jt < 8; ++jt)
#pragma unroll
            for (int q = 0; q < 4; ++q) acc[mt][jt][q] = 0.f;

    // staging index precompute
    const int arow  = t >> 1;
    const int ahalf = (t & 1) * 8;
    const int bkk   = t >> 4;
    const int bcol  = (t & 15) * 8;

    // ---------------- GEMM1: cat[128 x NSEG*128] @ w1 ----------------
    for (int kc = 0; kc < NSEG * D; kc += 16) {
        {   // stage A (gathered rows, tf32-converted)
            const float* ap = RP[(kc >> 7) * 128 + arow] + (kc & 127) + ahalf;
            float4 v0 = *(const float4*)ap;
            float4 v1 = *(const float4*)(ap + 4);
            uint32_t* ad = As + arow * AS_STRIDE + ahalf;
            ad[0] = f2tf(v0.x); ad[1] = f2tf(v0.y); ad[2] = f2tf(v0.z); ad[3] = f2tf(v0.w);
            ad[4] = f2tf(v1.x); ad[5] = f2tf(v1.y); ad[6] = f2tf(v1.z); ad[7] = f2tf(v1.w);
        }
        {   // stage B from w1
            const float* bp = w1 + (size_t)(kc + bkk) * D + bcol;
            float4 v0 = *(const float4*)bp;
            float4 v1 = *(const float4*)(bp + 4);
            uint32_t* bd = Bs + bkk * BS_STRIDE + bcol;
            bd[0] = f2tf(v0.x); bd[1] = f2tf(v0.y); bd[2] = f2tf(v0.z); bd[3] = f2tf(v0.w);
            bd[4] = f2tf(v1.x); bd[5] = f2tf(v1.y); bd[6] = f2tf(v1.z); bd[7] = f2tf(v1.w);
        }
        __syncthreads();
#pragma unroll
        for (int ks = 0; ks < 2; ++ks) {
            const int k0 = ks * 8;
            uint32_t a[2][4];
#pragma unroll
            for (int mt = 0; mt < 2; ++mt) {
                const uint32_t* ab = As + (rm + mt * 16 + g) * AS_STRIDE + k0 + c4;
                a[mt][0] = ab[0];
                a[mt][1] = ab[8 * AS_STRIDE];
                a[mt][2] = ab[4];
                a[mt][3] = ab[8 * AS_STRIDE + 4];
            }
#pragma unroll
            for (int jt = 0; jt < 8; ++jt) {
                const uint32_t* bb = Bs + (k0 + c4) * BS_STRIDE + wn * 64 + jt * 8 + g;
                uint32_t b[2];
                b[0] = bb[0];
                b[1] = bb[4 * BS_STRIDE];
                mma8(acc[0][jt], a[0], b);
                mma8(acc[1][jt], a[1], b);
            }
        }
        __syncthreads();
    }

    // bias1 + SiLU -> h (tf32-rounded) into Hs row-major
#pragma unroll
    for (int jt = 0; jt < 8; ++jt) {
        const int cb = wn * 64 + jt * 8 + 2 * c4;
        float2 bb = *(const float2*)(b1 + cb);
#pragma unroll
        for (int mt = 0; mt < 2; ++mt) {
            const int r0 = rm + mt * 16 + g;
            Hs[(size_t)r0 * HS_STRIDE + cb]           = __uint_as_float(f2tf(silu_f(acc[mt][jt][0] + bb.x)));
            Hs[(size_t)r0 * HS_STRIDE + cb + 1]       = __uint_as_float(f2tf(silu_f(acc[mt][jt][1] + bb.y)));
            Hs[(size_t)(r0 + 8) * HS_STRIDE + cb]     = __uint_as_float(f2tf(silu_f(acc[mt][jt][2] + bb.x)));
            Hs[(size_t)(r0 + 8) * HS_STRIDE + cb + 1] = __uint_as_float(f2tf(silu_f(acc[mt][jt][3] + bb.y)));
        }
    }
    __syncthreads();

#pragma unroll
    for (int mt = 0; mt < 2; ++mt)
#pragma unroll
        for (int jt = 0; jt < 8; ++jt)
#pragma unroll
            for (int q = 0; q < 4; ++q) acc[mt][jt][q] = 0.f;

    // ---------------- GEMM2: h[128x128] @ w2 ----------------
    for (int kc = 0; kc < D; kc += 16) {
        {   // stage B from w2
            const float* bp = w2 + (size_t)(kc + bkk) * D + bcol;
            float4 v0 = *(const float4*)bp;
            float4 v1 = *(const float4*)(bp + 4);
            uint32_t* bd = Bs + bkk * BS_STRIDE + bcol;
            bd[0] = f2tf(v0.x); bd[1] = f2tf(v0.y); bd[2] = f2tf(v0.z); bd[3] = f2tf(v0.w);
            bd[4] = f2tf(v1.x); bd[5] = f2tf(v1.y); bd[6] = f2tf(v1.z); bd[7] = f2tf(v1.w);
        }
        __syncthreads();
#pragma unroll
        for (int ks = 0; ks < 2; ++ks) {
            const int k0 = ks * 8;
            uint32_t a[2][4];
#pragma unroll
            for (int mt = 0; mt < 2; ++mt) {
                const float* ab = Hs + (size_t)(rm + mt * 16 + g) * HS_STRIDE + kc + k0 + c4;
                a[mt][0] = __float_as_uint(ab[0]);
                a[mt][1] = __float_as_uint(ab[8 * HS_STRIDE]);
                a[mt][2] = __float_as_uint(ab[4]);
                a[mt][3] = __float_as_uint(ab[8 * HS_STRIDE + 4]);
            }
#pragma unroll
            for (int jt = 0; jt < 8; ++jt) {
                const uint32_t* bb = Bs + (k0 + c4) * BS_STRIDE + wn * 64 + jt * 8 + g;
                uint32_t b[2];
                b[0] = bb[0];
                b[1] = bb[4 * BS_STRIDE];
                mma8(acc[0][jt], a[0], b);
                mma8(acc[1][jt], a[1], b);
            }
        }
        __syncthreads();
    }

    // y = acc + b2 -> Hs (fp32), overwriting h (safe: all GEMM2 reads done)
#pragma unroll
    for (int jt = 0; jt < 8; ++jt) {
        const int cb = wn * 64 + jt * 8 + 2 * c4;
        float2 bb = *(const float2*)(b2 + cb);
#pragma unroll
        for (int mt = 0; mt < 2; ++mt) {
            const int r0 = rm + mt * 16 + g;
            Hs[(size_t)r0 * HS_STRIDE + cb]           = acc[mt][jt][0] + bb.x;
            Hs[(size_t)r0 * HS_STRIDE + cb + 1]       = acc[mt][jt][1] + bb.y;
            Hs[(size_t)(r0 + 8) * HS_STRIDE + cb]     = acc[mt][jt][2] + bb.x;
            Hs[(size_t)(r0 + 8) * HS_STRIDE + cb + 1] = acc[mt][jt][3] + bb.y;
        }
    }
    __syncthreads();

    // ---------------- LayerNorm + output / scatter ----------------
    {
        float4 gm = *(const float4*)(gam + lane * 4);
        float4 bt = *(const float4*)(bet + lane * 4);
        for (int r = warp; r < 128; r += 8) {
            float4 v = *(const float4*)(Hs + (size_t)r * HS_STRIDE + lane * 4);
            float s  = v.x + v.y + v.z + v.w;
            float ss = fmaf(v.x, v.x, fmaf(v.y, v.y, fmaf(v.z, v.z, v.w * v.w)));
#pragma unroll
            for (int off = 16; off > 0; off >>= 1) {
                s  += __shfl_xor_sync(0xffffffffu, s, off);
                ss += __shfl_xor_sync(0xffffffffu, ss, off);
            }
            float mu  = s * (1.0f / 128.0f);
            float var = ss * (1.0f / 128.0f) - mu * mu;
            float rs  = rsqrtf(var + LNEPS);
            float4 o;
            o.x = (v.x - mu) * rs * gm.x + bt.x;
            o.y = (v.y - mu) * rs * gm.y + bt.y;
            o.z = (v.z - mu) * rs * gm.z + bt.z;
            o.w = (v.w - mu) * rs * gm.w + bt.w;
            int m = m0 + r;
            if (m < M) {
                if (MODE == 0) {
                    float* p = g_agg + (size_t)scat[m] * D + lane * 4;
                    atomicAdd(p + 0, o.x);
                    atomicAdd(p + 1, o.y);
                    atomicAdd(p + 2, o.z);
                    atomicAdd(p + 3, o.w);
                } else {
                    float4 rv = *(const float4*)(resid + (size_t)m * D + lane * 4);
                    o.x += rv.x; o.y += rv.y; o.z += rv.z; o.w += rv.w;
                    *(float4*)(outp + (size_t)m * D + lane * 4) = o;
                }
            }
        }
    }
}

extern "C" void kernel_launch(void* const* d_in, const int* in_sizes, int n_in,
                              void* d_out, int out_size) {
    const float* g2m  = (const float*)d_in[0];
    const float* grid = (const float*)d_in[1];
    const float* mesh = (const float*)d_in[2];
    const int*   src  = (const int*)d_in[3];
    const int*   dst  = (const int*)d_in[4];
    const float* ew1 = (const float*)d_in[5];
    const float* eb1 = (const float*)d_in[6];
    const float* ew2 = (const float*)d_in[7];
    const float* eb2 = (const float*)d_in[8];
    const float* eg  = (const float*)d_in[9];
    const float* ebt = (const float*)d_in[10];
    const float* sw1 = (const float*)d_in[11];
    const float* sb1 = (const float*)d_in[12];
    const float* sw2 = (const float*)d_in[13];
    const float* sb2 = (const float*)d_in[14];
    const float* sg  = (const float*)d_in[15];
    const float* sbt = (const float*)d_in[16];
    const float* dw1 = (const float*)d_in[17];
    const float* db1 = (const float*)d_in[18];
    const float* dw2 = (const float*)d_in[19];
    const float* db2 = (const float*)d_in[20];
    const float* dg  = (const float*)d_in[21];
    const float* dbt = (const float*)d_in[22];

    float* grid_out = (float*)d_out;                      // [NGRID, D] first
    float* mesh_out = grid_out + (size_t)NGRID * D;       // then [NMESH, D]

    const int SMEM_BASE = (AS_WORDS + BS_WORDS + HS_WORDS) * 4;  // 86528 B
    const int smem3 = SMEM_BASE + 3 * 128 * 8;
    const int smem2 = SMEM_BASE + 2 * 128 * 8;
    const int smem1 = SMEM_BASE + 1 * 128 * 8;

    cudaFuncSetAttribute(mlp_kernel<3,0>, cudaFuncAttributeMaxDynamicSharedMemorySize, smem3);
    cudaFuncSetAttribute(mlp_kernel<2,1>, cudaFuncAttributeMaxDynamicSharedMemorySize, smem2);
    cudaFuncSetAttribute(mlp_kernel<1,2>, cudaFuncAttributeMaxDynamicSharedMemorySize, smem1);

    // 1) zero the aggregation scratch
    zero_agg_kernel<<<(NMESH * D / 4 + 255) / 256, 256>>>();

    // 2) edge MLP (gathered concat) + LN + scatter-add into g_agg
    mlp_kernel<3,0><<<(NE + 127) / 128, 256, smem3>>>(
        g2m, grid, mesh, src, dst, NE,
        ew1, eb1, ew2, eb2, eg, ebt, nullptr, nullptr, dst);

    // 3) grid node MLP + residual
    mlp_kernel<1,2><<<(NGRID + 127) / 128, 256, smem1>>>(
        grid, nullptr, nullptr, nullptr, nullptr, NGRID,
        sw1, sb1, sw2, sb2, sg, sbt, grid, grid_out, nullptr);

    // 4) mesh node MLP on [agg | mesh] + residual
    mlp_kernel<2,1><<<(NMESH + 127) / 128, 256, smem2>>>(
        nullptr, mesh, nullptr, nullptr, nullptr, NMESH,
        dw1, db1, dw2, db2, dg, dbt, mesh, mesh_out, nullptr);
}

// round 4
// speedup vs baseline: 3.3931x; 1.1018x over previous
#include <cuda_runtime.h>
#include <cstdint>

#define D 128
#define NE 500000
#define NGRID 200000
#define NMESH 40000
#define LNEPS 1e-5f

#define AS_STRIDE 20                    // words per A row: 16 k + 4 pad (80B, 16B-aligned)
#define ASBUF_WORDS (128 * AS_STRIDE)   // 2560 words = 10 KB per buffer
#define BT_TILE 66                      // words per B frag tile: 32 lanes x 2 + 2 pad
#define BSBUF_WORDS (32 * BT_TILE)      // 2112 words = 8.25 KB per buffer
#define HS_STRIDE 132                   // 128 + 4 pad (528B, 16B-aligned)
#define HS_WORDS (128 * HS_STRIDE)
#define SMEM_WORDS (2 * ASBUF_WORDS + 2 * BSBUF_WORDS + HS_WORDS)  // 26240
#define ASBUF_BYTES (ASBUF_WORDS * 4)

// Scratch for scatter-add aggregation (allocation-free rule: __device__ global).
__device__ __align__(16) float g_agg[(size_t)NMESH * D];

__global__ void zero_agg_kernel() {
    size_t i = (size_t)blockIdx.x * blockDim.x + threadIdx.x;
    if (i < (size_t)NMESH * D / 4) {
        ((float4*)g_agg)[i] = make_float4(0.f, 0.f, 0.f, 0.f);
    }
}

__device__ __forceinline__ float silu_f(float x) {
    return x / (1.0f + __expf(-x));
}

__device__ __forceinline__ uint32_t f2tf(float x) {
    uint32_t r;
    asm("cvt.rna.tf32.f32 %0, %1;" : "=r"(r) : "f"(x));
    return r;
}

__device__ __forceinline__ void mma8(float* c, const uint32_t* a, const uint32_t* b) {
    asm volatile(
        "mma.sync.aligned.m16n8k8.row.col.f32.tf32.tf32.f32 "
        "{%0,%1,%2,%3}, {%4,%5,%6,%7}, {%8,%9}, {%0,%1,%2,%3};"
        : "+f"(c[0]), "+f"(c[1]), "+f"(c[2]), "+f"(c[3])
        : "r"(a[0]), "r"(a[1]), "r"(a[2]), "r"(a[3]), "r"(b[0]), "r"(b[1]));
}

// One LDSM.x4 = full m16k8 tf32 A-fragment (two b16 8x8 matrices per 8x8 tf32 tile).
__device__ __forceinline__ void ldsm4(uint32_t* r, uint32_t saddr) {
    asm volatile("ldmatrix.sync.aligned.m8n8.x4.shared.b16 {%0,%1,%2,%3}, [%4];"
                 : "=r"(r[0]), "=r"(r[1]), "=r"(r[2]), "=r"(r[3]) : "r"(saddr));
}

// Fused MLP via tf32 mma.sync: y = LN(silu(cat @ w1 + b1) @ w2 + b2) * g + b
// Block: 128 rows x 128 cols, 8 warps (4 m x 2 n), warp tile 32x64.
// MODE: 0 = edge (scatter-add to g_agg), 1 = mesh (seg0 = g_agg, residual), 2 = grid
template<int NSEG, int MODE>
__global__ __launch_bounds__(256, 2)
void mlp_kernel(const float* __restrict__ seg0,
                const float* __restrict__ seg1,
                const float* __restrict__ seg2,
                const int* __restrict__ idx1,
                const int* __restrict__ idx2,
                int M,
                const float* __restrict__ w1, const float* __restrict__ b1,
                const float* __restrict__ w2, const float* __restrict__ b2,
                const float* __restrict__ gam, const float* __restrict__ bet,
                const float* __restrict__ resid,
                float* __restrict__ outp,
                const int* __restrict__ scat)
{
    extern __shared__ uint32_t sm_u[];
    uint32_t* Bs0 = sm_u + 2 * ASBUF_WORDS;
    uint32_t* Bs1 = Bs0 + BSBUF_WORDS;
    float*    Hs  = (float*)(sm_u + 2 * ASBUF_WORDS + 2 * BSBUF_WORDS);

    const uint32_t As_sh = (uint32_t)__cvta_generic_to_shared(sm_u);
    const uint32_t Hs_sh = (uint32_t)__cvta_generic_to_shared(Hs);

    const int t    = threadIdx.x;
    const int lane = t & 31;
    const int warp = t >> 5;
    const int wm   = warp & 3;
    const int wn   = warp >> 2;
    const int m0   = blockIdx.x * 128;
    const int rm   = wm * 32;

    // LDSM lane geometry: row offset (lane&15), k half (lane>>4)*16 bytes
    const uint32_t a_row_base = (uint32_t)((rm + (lane & 15)) * (AS_STRIDE * 4) + (lane >> 4) * 16);
    const uint32_t h_row_base = (uint32_t)((rm + (lane & 15)) * (HS_STRIDE * 4) + (lane >> 4) * 16);

    // staging geometry
    const int arow  = t >> 1;            // A: row 0..127
    const int ahalf = (t & 1) * 8;       // A: k offset within 16-chunk
    const int bkk   = t >> 4;            // B: k within chunk (0..15)
    const int bntl  = t & 15;            // B: n-tile (0..15)
    const int bcol  = bntl * 8;
    const int bword = (((bkk >> 3) * 16 + bntl) * BT_TILE) + (bkk & 3) * 2 + ((bkk & 7) >> 2);

    // Gathered row pointers in registers (fixed per thread across chunks)
    const float* s0 = (MODE == 1) ? (const float*)g_agg : seg0;
    const int ma = min(m0 + arow, M - 1);
    const float* rp0 = s0 + (size_t)ma * D;
    const float* rp1 = nullptr;
    const float* rp2 = nullptr;
    if (NSEG >= 2) rp1 = seg1 + (size_t)((MODE == 0) ? idx1[ma] : ma) * D;
    if (NSEG >= 3) rp2 = seg2 + (size_t)idx2[ma] * D;

    float acc[2][8][4];
#pragma unroll
    for (int mt = 0; mt < 2; ++mt)
#pragma unroll
        for (int jt = 0; jt < 8; ++jt)
#pragma unroll
            for (int q = 0; q < 4; ++q) acc[mt][jt][q] = 0.f;

    float4 av0, av1, bv0, bv1;

    // ---- staging helpers (A gathered rows; B transposed to fragment order) ----
    auto ldA = [&](int c, float4& v0, float4& v1) {
        const int s = c >> 3;
        const float* base = (NSEG >= 3 && s == 2) ? rp2 : (NSEG >= 2 && s == 1) ? rp1 : rp0;
        const float* p = base + (c & 7) * 16 + ahalf;
        v0 = *(const float4*)p;
        v1 = *(const float4*)(p + 4);
    };
    auto stA = [&](uint32_t* buf, const float4& v0, const float4& v1) {
        uint32_t* d = buf + arow * AS_STRIDE + ahalf;
        d[0] = f2tf(v0.x); d[1] = f2tf(v0.y); d[2] = f2tf(v0.z); d[3] = f2tf(v0.w);
        d[4] = f2tf(v1.x); d[5] = f2tf(v1.y); d[6] = f2tf(v1.z); d[7] = f2tf(v1.w);
    };
    auto ldB = [&](const float* w, int c, float4& v0, float4& v1) {
        const float* p = w + (size_t)(c * 16 + bkk) * D + bcol;
        v0 = *(const float4*)p;
        v1 = *(const float4*)(p + 4);
    };
    auto stB = [&](uint32_t* buf, const float4& v0, const float4& v1) {
        uint32_t* d = buf + bword;
        d[0]  = f2tf(v0.x); d[8]  = f2tf(v0.y); d[16] = f2tf(v0.z); d[24] = f2tf(v0.w);
        d[32] = f2tf(v1.x); d[40] = f2tf(v1.y); d[48] = f2tf(v1.z); d[56] = f2tf(v1.w);
    };

    // ---------------- GEMM1: cat[128 x NSEG*128] @ w1 ----------------
    const int NC1 = NSEG * 8;
    ldA(0, av0, av1);
    ldB(w1, 0, bv0, bv1);
    stA(sm_u, av0, av1);
    stB(Bs0, bv0, bv1);
    __syncthreads();

    for (int c = 0; c < NC1; ++c) {
        const bool pf = (c + 1 < NC1);
        if (pf) { ldA(c + 1, av0, av1); ldB(w1, c + 1, bv0, bv1); }

        const uint32_t abuf = As_sh + ((c & 1) ? ASBUF_BYTES : 0) + a_row_base;
        const uint32_t* Bb = (c & 1) ? Bs1 : Bs0;
#pragma unroll
        for (int ks = 0; ks < 2; ++ks) {
            uint32_t a0f[4], a1f[4];
            ldsm4(a0f, abuf + ks * 32);
            ldsm4(a1f, abuf + 16 * (AS_STRIDE * 4) + ks * 32);
            uint2 bfr[8];
            const uint32_t* bt = Bb + (ks * 16 + wn * 8) * BT_TILE + lane * 2;
#pragma unroll
            for (int jt = 0; jt < 8; ++jt) bfr[jt] = *(const uint2*)(bt + jt * BT_TILE);
#pragma unroll
            for (int jt = 0; jt < 8; ++jt) {
                mma8(acc[0][jt], a0f, &bfr[jt].x);
                mma8(acc[1][jt], a1f, &bfr[jt].x);
            }
        }

        if (pf) {
            uint32_t* An = (c & 1) ? sm_u : sm_u + ASBUF_WORDS;
            uint32_t* Bn = (c & 1) ? Bs0 : Bs1;
            stA(An, av0, av1);
            stB(Bn, bv0, bv1);
        }
        __syncthreads();
    }

    // bias1 + SiLU -> h (tf32-rounded), row-major into Hs
    {
        const int g  = lane >> 2;
        const int c4 = lane & 3;
#pragma unroll
        for (int jt = 0; jt < 8; ++jt) {
            const int cb = wn * 64 + jt * 8 + 2 * c4;
            float2 bb = *(const float2*)(b1 + cb);
#pragma unroll
            for (int mt = 0; mt < 2; ++mt) {
                const int r0 = rm + mt * 16 + g;
                Hs[(size_t)r0 * HS_STRIDE + cb]           = __uint_as_float(f2tf(silu_f(acc[mt][jt][0] + bb.x)));
                Hs[(size_t)r0 * HS_STRIDE + cb + 1]       = __uint_as_float(f2tf(silu_f(acc[mt][jt][1] + bb.y)));
                Hs[(size_t)(r0 + 8) * HS_STRIDE + cb]     = __uint_as_float(f2tf(silu_f(acc[mt][jt][2] + bb.x)));
                Hs[(size_t)(r0 + 8) * HS_STRIDE + cb + 1] = __uint_as_float(f2tf(silu_f(acc[mt][jt][3] + bb.y)));
            }
        }
    }

#pragma unroll
    for (int mt = 0; mt < 2; ++mt)
#pragma unroll
        for (int jt = 0; jt < 8; ++jt)
#pragma unroll
            for (int q = 0; q < 4; ++q) acc[mt][jt][q] = 0.f;

    // ---------------- GEMM2: h[128x128] @ w2 (A-frags LDSM'd from Hs) ----------------
    ldB(w2, 0, bv0, bv1);
    stB(Bs0, bv0, bv1);
    __syncthreads();   // covers Hs writes + Bs0

    for (int c = 0; c < 8; ++c) {
        const bool pf = (c + 1 < 8);
        if (pf) ldB(w2, c + 1, bv0, bv1);

        const uint32_t hb = Hs_sh + h_row_base + (uint32_t)(c * 64);  // c*16 floats
        const uint32_t* Bb = (c & 1) ? Bs1 : Bs0;
#pragma unroll
        for (int ks = 0; ks < 2; ++ks) {
            uint32_t a0f[4], a1f[4];
            ldsm4(a0f, hb + ks * 32);
            ldsm4(a1f, hb + 16 * (HS_STRIDE * 4) + ks * 32);
            uint2 bfr[8];
            const uint32_t* bt = Bb + (ks * 16 + wn * 8) * BT_TILE + lane * 2;
#pragma unroll
            for (int jt = 0; jt < 8; ++jt) bfr[jt] = *(const uint2*)(bt + jt * BT_TILE);
#pragma unroll
            for (int jt = 0; jt < 8; ++jt) {
                mma8(acc[0][jt], a0f, &bfr[jt].x);
                mma8(acc[1][jt], a1f, &bfr[jt].x);
            }
        }

        if (pf) stB((c & 1) ? Bs0 : Bs1, bv0, bv1);
        __syncthreads();
    }

    // y = acc + b2 -> Hs (fp32), overwriting h (all GEMM2 reads complete after last sync)
    {
        const int g  = lane >> 2;
        const int c4 = lane & 3;
#pragma unroll
        for (int jt = 0; jt < 8; ++jt) {
            const int cb = wn * 64 + jt * 8 + 2 * c4;
            float2 bb = *(const float2*)(b2 + cb);
#pragma unroll
            for (int mt = 0; mt < 2; ++mt) {
                const int r0 = rm + mt * 16 + g;
                Hs[(size_t)r0 * HS_STRIDE + cb]           = acc[mt][jt][0] + bb.x;
                Hs[(size_t)r0 * HS_STRIDE + cb + 1]       = acc[mt][jt][1] + bb.y;
                Hs[(size_t)(r0 + 8) * HS_STRIDE + cb]     = acc[mt][jt][2] + bb.x;
                Hs[(size_t)(r0 + 8) * HS_STRIDE + cb + 1] = acc[mt][jt][3] + bb.y;
            }
        }
    }
    __syncthreads();

    // ---------------- LayerNorm + output / scatter ----------------
    {
        float4 gm = *(const float4*)(gam + lane * 4);
        float4 bt = *(const float4*)(bet + lane * 4);
        for (int r = warp; r < 128; r += 8) {
            float4 v = *(const float4*)(Hs + (size_t)r * HS_STRIDE + lane * 4);
            float s  = v.x + v.y + v.z + v.w;
            float ss = fmaf(v.x, v.x, fmaf(v.y, v.y, fmaf(v.z, v.z, v.w * v.w)));
#pragma unroll
            for (int off = 16; off > 0; off >>= 1) {
                s  += __shfl_xor_sync(0xffffffffu, s, off);
                ss += __shfl_xor_sync(0xffffffffu, ss, off);
            }
            float mu  = s * (1.0f / 128.0f);
            float var = ss * (1.0f / 128.0f) - mu * mu;
            float rs  = rsqrtf(var + LNEPS);
            float4 o;
            o.x = (v.x - mu) * rs * gm.x + bt.x;
            o.y = (v.y - mu) * rs * gm.y + bt.y;
            o.z = (v.z - mu) * rs * gm.z + bt.z;
            o.w = (v.w - mu) * rs * gm.w + bt.w;
            int m = m0 + r;
            if (m < M) {
                if (MODE == 0) {
                    float* p = g_agg + (size_t)scat[m] * D + lane * 4;
                    atomicAdd(p + 0, o.x);
                    atomicAdd(p + 1, o.y);
                    atomicAdd(p + 2, o.z);
                    atomicAdd(p + 3, o.w);
                } else {
                    float4 rv = *(const float4*)(resid + (size_t)m * D + lane * 4);
                    o.x += rv.x; o.y += rv.y; o.z += rv.z; o.w += rv.w;
                    *(float4*)(outp + (size_t)m * D + lane * 4) = o;
                }
            }
        }
    }
}

extern "C" void kernel_launch(void* const* d_in, const int* in_sizes, int n_in,
                              void* d_out, int out_size) {
    const float* g2m  = (const float*)d_in[0];
    const float* grid = (const float*)d_in[1];
    const float* mesh = (const float*)d_in[2];
    const int*   src  = (const int*)d_in[3];
    const int*   dst  = (const int*)d_in[4];
    const float* ew1 = (const float*)d_in[5];
    const float* eb1 = (const float*)d_in[6];
    const float* ew2 = (const float*)d_in[7];
    const float* eb2 = (const float*)d_in[8];
    const float* eg  = (const float*)d_in[9];
    const float* ebt = (const float*)d_in[10];
    const float* sw1 = (const float*)d_in[11];
    const float* sb1 = (const float*)d_in[12];
    const float* sw2 = (const float*)d_in[13];
    const float* sb2 = (const float*)d_in[14];
    const float* sg  = (const float*)d_in[15];
    const float* sbt = (const float*)d_in[16];
    const float* dw1 = (const float*)d_in[17];
    const float* db1 = (const float*)d_in[18];
    const float* dw2 = (const float*)d_in[19];
    const float* db2 = (const float*)d_in[20];
    const float* dg  = (const float*)d_in[21];
    const float* dbt = (const float*)d_in[22];

    float* grid_out = (float*)d_out;                  // [NGRID, D] first
    float* mesh_out = grid_out + (size_t)NGRID * D;   // then [NMESH, D]

    const int smem = SMEM_WORDS * 4;  // 104960 B

    cudaFuncSetAttribute(mlp_kernel<3,0>, cudaFuncAttributeMaxDynamicSharedMemorySize, smem);
    cudaFuncSetAttribute(mlp_kernel<2,1>, cudaFuncAttributeMaxDynamicSharedMemorySize, smem);
    cudaFuncSetAttribute(mlp_kernel<1,2>, cudaFuncAttributeMaxDynamicSharedMemorySize, smem);

    // 1) zero the aggregation scratch
    zero_agg_kernel<<<(NMESH * D / 4 + 255) / 256, 256>>>();

    // 2) edge MLP (gathered concat) + LN + scatter-add into g_agg
    mlp_kernel<3,0><<<(NE + 127) / 128, 256, smem>>>(
        g2m, grid, mesh, src, dst, NE,
        ew1, eb1, ew2, eb2, eg, ebt, nullptr, nullptr, dst);

    // 3) grid node MLP + residual
    mlp_kernel<1,2><<<(NGRID + 127) / 128, 256, smem>>>(
        grid, nullptr, nullptr, nullptr, nullptr, NGRID,
        sw1, sb1, sw2, sb2, sg, sbt, grid, grid_out, nullptr);

    // 4) mesh node MLP on [agg | mesh] + residual
    mlp_kernel<2,1><<<(NMESH + 127) / 128, 256, smem>>>(
        nullptr, mesh, nullptr, nullptr, nullptr, NMESH,
        dw1, db1, dw2, db2, dg, dbt, mesh, mesh_out, nullptr);
}

// round 6
// speedup vs baseline: 3.4125x; 1.0057x over previous
#include <cuda_runtime.h>
#include <cstdint>

#define D 128
#define NE 500000
#define NGRID 200000
#define NMESH 40000
#define LNEPS 1e-5f

#define AS_STRIDE 20                    // words per A row: 16 k + 4 pad (80B, 16B-aligned)
#define ASBUF_WORDS (128 * AS_STRIDE)   // 2560 words = 10 KB per buffer
#define BT_TILE 66                      // words per B frag tile: 32 lanes x 2 + 2 pad
#define BSBUF_WORDS (32 * BT_TILE)      // 2112 words = 8.25 KB per buffer
#define HS_STRIDE 132                   // 128 + 4 pad (528B, 16B-aligned)
#define HS_WORDS (128 * HS_STRIDE)
#define SMEM_WORDS (2 * ASBUF_WORDS + 2 * BSBUF_WORDS + HS_WORDS)  // 26240
#define ASBUF_BYTES (ASBUF_WORDS * 4)

// Scratch for scatter-add aggregation (allocation-free rule: __device__ global).
__device__ __align__(16) float g_agg[(size_t)NMESH * D];

__global__ void zero_agg_kernel() {
    size_t i = (size_t)blockIdx.x * blockDim.x + threadIdx.x;
    if (i < (size_t)NMESH * D / 4) {
        ((float4*)g_agg)[i] = make_float4(0.f, 0.f, 0.f, 0.f);
    }
}

__device__ __forceinline__ float silu_f(float x) {
    return x / (1.0f + __expf(-x));
}

__device__ __forceinline__ uint32_t f2tf(float x) {
    uint32_t r;
    asm("cvt.rna.tf32.f32 %0, %1;" : "=r"(r) : "f"(x));
    return r;
}

__device__ __forceinline__ void mma8(float* c, const uint32_t* a, const uint32_t* b) {
    asm volatile(
        "mma.sync.aligned.m16n8k8.row.col.f32.tf32.tf32.f32 "
        "{%0,%1,%2,%3}, {%4,%5,%6,%7}, {%8,%9}, {%0,%1,%2,%3};"
        : "+f"(c[0]), "+f"(c[1]), "+f"(c[2]), "+f"(c[3])
        : "r"(a[0]), "r"(a[1]), "r"(a[2]), "r"(a[3]), "r"(b[0]), "r"(b[1]));
}

// One LDSM.x4 = full m16k8 tf32 A-fragment (two b16 8x8 matrices per 8x8 tf32 tile).
__device__ __forceinline__ void ldsm4(uint32_t* r, uint32_t saddr) {
    asm volatile("ldmatrix.sync.aligned.m8n8.x4.shared.b16 {%0,%1,%2,%3}, [%4];"
                 : "=r"(r[0]), "=r"(r[1]), "=r"(r[2]), "=r"(r[3]) : "r"(saddr));
}

// Fused MLP via tf32 mma.sync: y = LN(silu(cat @ w1 + b1) @ w2 + b2) * g + b
// Block: 128 rows x 128 cols, 8 warps (4 m x 2 n), warp tile 32x64.
// MODE: 0 = edge (scatter-add to g_agg), 1 = mesh (seg0 = g_agg, residual), 2 = grid
template<int NSEG, int MODE>
__global__ __launch_bounds__(256, 2)
void mlp_kernel(const float* __restrict__ seg0,
                const float* __restrict__ seg1,
                const float* __restrict__ seg2,
                const int* __restrict__ idx1,
                const int* __restrict__ idx2,
                int M,
                const float* __restrict__ w1, const float* __restrict__ b1,
                const float* __restrict__ w2, const float* __restrict__ b2,
                const float* __restrict__ gam, const float* __restrict__ bet,
                const float* __restrict__ resid,
                float* __restrict__ outp,
                const int* __restrict__ scat)
{
    extern __shared__ uint32_t sm_u[];
    uint32_t* Bs0 = sm_u + 2 * ASBUF_WORDS;
    uint32_t* Bs1 = Bs0 + BSBUF_WORDS;
    float*    Hs  = (float*)(sm_u + 2 * ASBUF_WORDS + 2 * BSBUF_WORDS);

    const uint32_t As_sh = (uint32_t)__cvta_generic_to_shared(sm_u);
    const uint32_t Hs_sh = (uint32_t)__cvta_generic_to_shared(Hs);

    const int t    = threadIdx.x;
    const int lane = t & 31;
    const int warp = t >> 5;
    const int wm   = warp & 3;
    const int wn   = warp >> 2;
    const int m0   = blockIdx.x * 128;
    const int rm   = wm * 32;

    // LDSM lane geometry: row offset (lane&15), k half (lane>>4)*16 bytes
    const uint32_t a_row_base = (uint32_t)((rm + (lane & 15)) * (AS_STRIDE * 4) + (lane >> 4) * 16);
    const uint32_t h_row_base = (uint32_t)((rm + (lane & 15)) * (HS_STRIDE * 4) + (lane >> 4) * 16);

    // staging geometry
    const int arow  = t >> 1;            // A: row 0..127
    const int ahalf = (t & 1) * 8;       // A: k offset within 16-chunk
    const int bkk   = t >> 4;            // B: k within chunk (0..15)
    const int bntl  = t & 15;            // B: n-tile (0..15)
    const int bcol  = bntl * 8;
    const int bword = (((bkk >> 3) * 16 + bntl) * BT_TILE) + (bkk & 3) * 2 + ((bkk & 7) >> 2);

    // Gathered row pointers in registers (fixed per thread across chunks)
    const float* s0 = (MODE == 1) ? (const float*)g_agg : seg0;
    const int ma = min(m0 + arow, M - 1);
    const float* rp0 = s0 + (size_t)ma * D;
    const float* rp1 = nullptr;
    const float* rp2 = nullptr;
    if (NSEG >= 2) rp1 = seg1 + (size_t)((MODE == 0) ? idx1[ma] : ma) * D;
    if (NSEG >= 3) rp2 = seg2 + (size_t)idx2[ma] * D;

    float acc[2][8][4];
#pragma unroll
    for (int mt = 0; mt < 2; ++mt)
#pragma unroll
        for (int jt = 0; jt < 8; ++jt)
#pragma unroll
            for (int q = 0; q < 4; ++q) acc[mt][jt][q] = 0.f;

    float4 av0, av1, bv0, bv1;

    // ---- staging helpers (A gathered rows; B transposed to fragment order) ----
    auto ldA = [&](int c, float4& v0, float4& v1) {
        const int s = c >> 3;
        const float* base = (NSEG >= 3 && s == 2) ? rp2 : (NSEG >= 2 && s == 1) ? rp1 : rp0;
        const float* p = base + (c & 7) * 16 + ahalf;
        v0 = *(const float4*)p;
        v1 = *(const float4*)(p + 4);
    };
    auto stA = [&](uint32_t* buf, const float4& v0, const float4& v1) {
        uint32_t* d = buf + arow * AS_STRIDE + ahalf;
        d[0] = f2tf(v0.x); d[1] = f2tf(v0.y); d[2] = f2tf(v0.z); d[3] = f2tf(v0.w);
        d[4] = f2tf(v1.x); d[5] = f2tf(v1.y); d[6] = f2tf(v1.z); d[7] = f2tf(v1.w);
    };
    auto ldB = [&](const float* w, int c, float4& v0, float4& v1) {
        const float* p = w + (size_t)(c * 16 + bkk) * D + bcol;
        v0 = *(const float4*)p;
        v1 = *(const float4*)(p + 4);
    };
    auto stB = [&](uint32_t* buf, const float4& v0, const float4& v1) {
        uint32_t* d = buf + bword;
        d[0]  = f2tf(v0.x); d[8]  = f2tf(v0.y); d[16] = f2tf(v0.z); d[24] = f2tf(v0.w);
        d[32] = f2tf(v1.x); d[40] = f2tf(v1.y); d[48] = f2tf(v1.z); d[56] = f2tf(v1.w);
    };

    // ---------------- GEMM1: cat[128 x NSEG*128] @ w1 ----------------
    const int NC1 = NSEG * 8;
    ldA(0, av0, av1);
    ldB(w1, 0, bv0, bv1);
    stA(sm_u, av0, av1);
    stB(Bs0, bv0, bv1);
    __syncthreads();

    for (int c = 0; c < NC1; ++c) {
        const bool pf = (c + 1 < NC1);
        if (pf) { ldA(c + 1, av0, av1); ldB(w1, c + 1, bv0, bv1); }

        const uint32_t abuf = As_sh + ((c & 1) ? ASBUF_BYTES : 0) + a_row_base;
        const uint32_t* Bb = (c & 1) ? Bs1 : Bs0;
#pragma unroll
        for (int ks = 0; ks < 2; ++ks) {
            uint32_t a0f[4], a1f[4];
            ldsm4(a0f, abuf + ks * 32);
            ldsm4(a1f, abuf + 16 * (AS_STRIDE * 4) + ks * 32);
            uint2 bfr[8];
            const uint32_t* bt = Bb + (ks * 16 + wn * 8) * BT_TILE + lane * 2;
#pragma unroll
            for (int jt = 0; jt < 8; ++jt) bfr[jt] = *(const uint2*)(bt + jt * BT_TILE);
#pragma unroll
            for (int jt = 0; jt < 8; ++jt) {
                mma8(acc[0][jt], a0f, &bfr[jt].x);
                mma8(acc[1][jt], a1f, &bfr[jt].x);
            }
        }

        if (pf) {
            uint32_t* An = (c & 1) ? sm_u : sm_u + ASBUF_WORDS;
            uint32_t* Bn = (c & 1) ? Bs0 : Bs1;
            stA(An, av0, av1);
            stB(Bn, bv0, bv1);
        }
        __syncthreads();
    }

    // bias1 + SiLU -> h (tf32-rounded), row-major into Hs
    {
        const int g  = lane >> 2;
        const int c4 = lane & 3;
#pragma unroll
        for (int jt = 0; jt < 8; ++jt) {
            const int cb = wn * 64 + jt * 8 + 2 * c4;
            float2 bb = *(const float2*)(b1 + cb);
#pragma unroll
            for (int mt = 0; mt < 2; ++mt) {
                const int r0 = rm + mt * 16 + g;
                Hs[(size_t)r0 * HS_STRIDE + cb]           = __uint_as_float(f2tf(silu_f(acc[mt][jt][0] + bb.x)));
                Hs[(size_t)r0 * HS_STRIDE + cb + 1]       = __uint_as_float(f2tf(silu_f(acc[mt][jt][1] + bb.y)));
                Hs[(size_t)(r0 + 8) * HS_STRIDE + cb]     = __uint_as_float(f2tf(silu_f(acc[mt][jt][2] + bb.x)));
                Hs[(size_t)(r0 + 8) * HS_STRIDE + cb + 1] = __uint_as_float(f2tf(silu_f(acc[mt][jt][3] + bb.y)));
            }
        }
    }

#pragma unroll
    for (int mt = 0; mt < 2; ++mt)
#pragma unroll
        for (int jt = 0; jt < 8; ++jt)
#pragma unroll
            for (int q = 0; q < 4; ++q) acc[mt][jt][q] = 0.f;

    // ---------------- GEMM2: h[128x128] @ w2 (A-frags LDSM'd from Hs) ----------------
    ldB(w2, 0, bv0, bv1);
    stB(Bs0, bv0, bv1);
    __syncthreads();   // covers Hs writes + Bs0

    for (int c = 0; c < 8; ++c) {
        const bool pf = (c + 1 < 8);
        if (pf) ldB(w2, c + 1, bv0, bv1);

        const uint32_t hb = Hs_sh + h_row_base + (uint32_t)(c * 64);  // c*16 floats
        const uint32_t* Bb = (c & 1) ? Bs1 : Bs0;
#pragma unroll
        for (int ks = 0; ks < 2; ++ks) {
            uint32_t a0f[4], a1f[4];
            ldsm4(a0f, hb + ks * 32);
            ldsm4(a1f, hb + 16 * (HS_STRIDE * 4) + ks * 32);
            uint2 bfr[8];
            const uint32_t* bt = Bb + (ks * 16 + wn * 8) * BT_TILE + lane * 2;
#pragma unroll
            for (int jt = 0; jt < 8; ++jt) bfr[jt] = *(const uint2*)(bt + jt * BT_TILE);
#pragma unroll
            for (int jt = 0; jt < 8; ++jt) {
                mma8(acc[0][jt], a0f, &bfr[jt].x);
                mma8(acc[1][jt], a1f, &bfr[jt].x);
            }
        }

        if (pf) stB((c & 1) ? Bs0 : Bs1, bv0, bv1);
        __syncthreads();
    }

    // y = acc + b2 -> Hs (fp32), overwriting h (all GEMM2 reads complete after last sync)
    {
        const int g  = lane >> 2;
        const int c4 = lane & 3;
#pragma unroll
        for (int jt = 0; jt < 8; ++jt) {
            const int cb = wn * 64 + jt * 8 + 2 * c4;
            float2 bb = *(const float2*)(b2 + cb);
#pragma unroll
            for (int mt = 0; mt < 2; ++mt) {
                const int r0 = rm + mt * 16 + g;
                Hs[(size_t)r0 * HS_STRIDE + cb]           = acc[mt][jt][0] + bb.x;
                Hs[(size_t)r0 * HS_STRIDE + cb + 1]       = acc[mt][jt][1] + bb.y;
                Hs[(size_t)(r0 + 8) * HS_STRIDE + cb]     = acc[mt][jt][2] + bb.x;
                Hs[(size_t)(r0 + 8) * HS_STRIDE + cb + 1] = acc[mt][jt][3] + bb.y;
            }
        }
    }
    __syncthreads();

    // ---------------- LayerNorm + output / scatter ----------------
    {
        float4 gm = *(const float4*)(gam + lane * 4);
        float4 bt = *(const float4*)(bet + lane * 4);
        for (int r = warp; r < 128; r += 8) {
            float4 v = *(const float4*)(Hs + (size_t)r * HS_STRIDE + lane * 4);
            float s  = v.x + v.y + v.z + v.w;
            float ss = fmaf(v.x, v.x, fmaf(v.y, v.y, fmaf(v.z, v.z, v.w * v.w)));
#pragma unroll
            for (int off = 16; off > 0; off >>= 1) {
                s  += __shfl_xor_sync(0xffffffffu, s, off);
                ss += __shfl_xor_sync(0xffffffffu, ss, off);
            }
            float mu  = s * (1.0f / 128.0f);
            float var = ss * (1.0f / 128.0f) - mu * mu;
            float rs  = rsqrtf(var + LNEPS);
            float4 o;
            o.x = (v.x - mu) * rs * gm.x + bt.x;
            o.y = (v.y - mu) * rs * gm.y + bt.y;
            o.z = (v.z - mu) * rs * gm.z + bt.z;
            o.w = (v.w - mu) * rs * gm.w + bt.w;
            int m = m0 + r;
            if (m < M) {
                if (MODE == 0) {
                    float* p = g_agg + (size_t)scat[m] * D + lane * 4;
                    atomicAdd(p + 0, o.x);
                    atomicAdd(p + 1, o.y);
                    atomicAdd(p + 2, o.z);
                    atomicAdd(p + 3, o.w);
                } else {
                    float4 rv = *(const float4*)(resid + (size_t)m * D + lane * 4);
                    o.x += rv.x; o.y += rv.y; o.z += rv.z; o.w += rv.w;
                    *(float4*)(outp + (size_t)m * D + lane * 4) = o;
                }
            }
        }
    }
}

extern "C" void kernel_launch(void* const* d_in, const int* in_sizes, int n_in,
                              void* d_out, int out_size) {
    const float* g2m  = (const float*)d_in[0];
    const float* grid = (const float*)d_in[1];
    const float* mesh = (const float*)d_in[2];
    const int*   src  = (const int*)d_in[3];
    const int*   dst  = (const int*)d_in[4];
    const float* ew1 = (const float*)d_in[5];
    const float* eb1 = (const float*)d_in[6];
    const float* ew2 = (const float*)d_in[7];
    const float* eb2 = (const float*)d_in[8];
    const float* eg  = (const float*)d_in[9];
    const float* ebt = (const float*)d_in[10];
    const float* sw1 = (const float*)d_in[11];
    const float* sb1 = (const float*)d_in[12];
    const float* sw2 = (const float*)d_in[13];
    const float* sb2 = (const float*)d_in[14];
    const float* sg  = (const float*)d_in[15];
    const float* sbt = (const float*)d_in[16];
    const float* dw1 = (const float*)d_in[17];
    const float* db1 = (const float*)d_in[18];
    const float* dw2 = (const float*)d_in[19];
    const float* db2 = (const float*)d_in[20];
    const float* dg  = (const float*)d_in[21];
    const float* dbt = (const float*)d_in[22];

    float* grid_out = (float*)d_out;                  // [NGRID, D] first
    float* mesh_out = grid_out + (size_t)NGRID * D;   // then [NMESH, D]

    const int smem = SMEM_WORDS * 4;  // 104960 B

    cudaFuncSetAttribute(mlp_kernel<3,0>, cudaFuncAttributeMaxDynamicSharedMemorySize, smem);
    cudaFuncSetAttribute(mlp_kernel<2,1>, cudaFuncAttributeMaxDynamicSharedMemorySize, smem);
    cudaFuncSetAttribute(mlp_kernel<1,2>, cudaFuncAttributeMaxDynamicSharedMemorySize, smem);

    // 1) zero the aggregation scratch
    zero_agg_kernel<<<(NMESH * D / 4 + 255) / 256, 256>>>();

    // 2) edge MLP (gathered concat) + LN + scatter-add into g_agg
    mlp_kernel<3,0><<<(NE + 127) / 128, 256, smem>>>(
        g2m, grid, mesh, src, dst, NE,
        ew1, eb1, ew2, eb2, eg, ebt, nullptr, nullptr, dst);

    // 3) grid node MLP + residual
    mlp_kernel<1,2><<<(NGRID + 127) / 128, 256, smem>>>(
        grid, nullptr, nullptr, nullptr, nullptr, NGRID,
        sw1, sb1, sw2, sb2, sg, sbt, grid, grid_out, nullptr);

    // 4) mesh node MLP on [agg | mesh] + residual
    mlp_kernel<2,1><<<(NMESH + 127) / 128, 256, smem>>>(
        nullptr, mesh, nullptr, nullptr, nullptr, NMESH,
        dw1, db1, dw2, db2, dg, dbt, mesh, mesh_out, nullptr);
}

// round 8
// speedup vs baseline: 5.4902x; 1.6088x over previous
#include <cuda_runtime.h>
#include <cuda_fp16.h>
#include <cstdint>

#define D 128
#define NE 500000
#define NGRID 200000
#define NMESH 40000
#define LNEPS 1e-5f

// smem byte layout
#define SM_PART 0          // float2 partials[2][128] = 2048 B
#define SM_A0   4096       // A chunks: 2 x (128 rows x 80 B)
#define SM_B0   24576      // B chunks: 2 x (128 rows x 80 B)
#define SM_HS   45056      // h: 128 rows x 272 B (half)
#define SM_TOTAL 79872
#define ABUF 10240
#define ARS  80            // A/B row stride (32 halves + 8 pad)
#define HRS  272           // Hs row stride (128 halves + 8 pad)

// g_wTh offsets (half elements): [N=128][K] K-contig
#define WT_E1 0
#define WT_E2 49152
#define WT_S1 65536
#define WT_S2 81920
#define WT_D1 98304
#define WT_D2 131072
#define WT_TOTAL 147456

__device__ __align__(16) float g_agg[(size_t)NMESH * D];
__device__ __align__(16) __half g_wTh[WT_TOTAL];

__device__ __forceinline__ float silu_f(float x) { return x / (1.0f + __expf(-x)); }

__device__ __forceinline__ uint32_t pack2(float x, float y) {
    __half2 h = __floats2half2_rn(x, y);
    return *reinterpret_cast<uint32_t*>(&h);
}

__device__ __forceinline__ void mma16(float* c, const uint32_t* a, const uint32_t* b) {
    asm volatile(
        "mma.sync.aligned.m16n8k16.row.col.f32.f16.f16.f32 "
        "{%0,%1,%2,%3}, {%4,%5,%6,%7}, {%8,%9}, {%0,%1,%2,%3};"
        : "+f"(c[0]), "+f"(c[1]), "+f"(c[2]), "+f"(c[3])
        : "r"(a[0]), "r"(a[1]), "r"(a[2]), "r"(a[3]), "r"(b[0]), "r"(b[1]));
}

__device__ __forceinline__ void ldsm4(uint32_t* r, uint32_t saddr) {
    asm volatile("ldmatrix.sync.aligned.m8n8.x4.shared.b16 {%0,%1,%2,%3}, [%4];"
                 : "=r"(r[0]), "=r"(r[1]), "=r"(r[2]), "=r"(r[3]) : "r"(saddr));
}

__global__ void zero_agg_kernel() {
    size_t i = (size_t)blockIdx.x * blockDim.x + threadIdx.x;
    if (i < (size_t)NMESH * D / 4)
        ((float4*)g_agg)[i] = make_float4(0.f, 0.f, 0.f, 0.f);
}

__global__ void prep_kernel(const float* __restrict__ ew1, const float* __restrict__ ew2,
                            const float* __restrict__ sw1, const float* __restrict__ sw2,
                            const float* __restrict__ dw1, const float* __restrict__ dw2) {
    int i = blockIdx.x * blockDim.x + threadIdx.x;
    if (i >= WT_TOTAL) return;
    const float* src; int off, K;
    if (i < WT_E2)      { src = ew1; off = WT_E1; K = 384; }
    else if (i < WT_S1) { src = ew2; off = WT_E2; K = 128; }
    else if (i < WT_S2) { src = sw1; off = WT_S1; K = 128; }
    else if (i < WT_D1) { src = sw2; off = WT_S2; K = 128; }
    else if (i < WT_D2) { src = dw1; off = WT_D1; K = 256; }
    else                { src = dw2; off = WT_D2; K = 128; }
    int j = i - off;
    int n = j / K, k = j - n * K;
    g_wTh[i] = __float2half_rn(src[(size_t)k * 128 + n]);
}

// Fused MLP via fp16 mma.sync m16n8k16; fp32 accumulate; register LayerNorm.
// Block: 128 rows x 128 cols, 8 warps (4 m x 2 n), warp tile 32x64.
// MODE: 0 = edge (scatter-add to g_agg), 1 = mesh (seg0=g_agg, residual), 2 = grid
template<int NSEG, int MODE>
__global__ __launch_bounds__(256, 2)
void mlp_kernel(const float* __restrict__ seg0, const float* __restrict__ seg1,
                const float* __restrict__ seg2,
                const int* __restrict__ idx1, const int* __restrict__ idx2,
                int M, int wt1_off, int wt2_off,
                const float* __restrict__ b1, const float* __restrict__ b2,
                const float* __restrict__ gam, const float* __restrict__ bet,
                const float* __restrict__ resid, float* __restrict__ outp,
                const int* __restrict__ scat)
{
    extern __shared__ char smem[];
    const uint32_t sbase = (uint32_t)__cvta_generic_to_shared(smem);

    const int t    = threadIdx.x;
    const int lane = t & 31;
    const int warp = t >> 5;
    const int wm   = warp & 3;
    const int wn   = warp >> 2;
    const int m0   = blockIdx.x * 128;
    const int rm   = wm * 32;
    const int g    = lane >> 2;
    const int c4   = lane & 3;
    const int cb0  = wn * 64 + 2 * c4;

    // ldmatrix lane geometry
    const uint32_t a_geo = (uint32_t)((rm + (lane & 15)) * ARS + (lane >> 4) * 16);
    const uint32_t b_geo = (uint32_t)((wn * 64 + ((lane >> 4) << 3) + (lane & 7)) * ARS
                                      + ((lane >> 3) & 1) * 16);
    const uint32_t h_geo = (uint32_t)((rm + (lane & 15)) * HRS + (lane >> 4) * 16);

    // gathered row pointers (clamped tail; writes guarded later)
    const float* s0 = (MODE == 1) ? (const float*)g_agg : seg0;
    const int ma = min(m0 + (t >> 1), M - 1);
    const float* rp0 = s0 + (size_t)ma * D;
    const float* rp1 = (NSEG >= 2) ? seg1 + (size_t)((MODE == 0) ? idx1[ma] : ma) * D : nullptr;
    const float* rp2 = (NSEG >= 3) ? seg2 + (size_t)idx2[ma] * D : nullptr;

    const __half* wt1 = g_wTh + wt1_off;
    const __half* wt2 = g_wTh + wt2_off;
    const int KT1 = NSEG * 128;

    float acc[2][8][4];
#pragma unroll
    for (int mt = 0; mt < 2; ++mt)
#pragma unroll
        for (int jt = 0; jt < 8; ++jt)
#pragma unroll
            for (int q = 0; q < 4; ++q) acc[mt][jt][q] = 0.f;

    float4 aR[4];
    uint4 bU[2];

    auto ldgA = [&](int c) {
        const float* base = rp0;
        if (NSEG >= 2 && (c >> 2) == 1) base = rp1;
        if (NSEG >= 3 && (c >> 2) == 2) base = rp2;
        const float4* p = (const float4*)(base + (c & 3) * 32 + (t & 1) * 16);
        aR[0] = p[0]; aR[1] = p[1]; aR[2] = p[2]; aR[3] = p[3];
    };
    auto stsA = [&](int slot) {
        char* dst = smem + SM_A0 + slot * ABUF + (t >> 1) * ARS + (t & 1) * 32;
        uint4 u0, u1;
        u0.x = pack2(aR[0].x, aR[0].y); u0.y = pack2(aR[0].z, aR[0].w);
        u0.z = pack2(aR[1].x, aR[1].y); u0.w = pack2(aR[1].z, aR[1].w);
        u1.x = pack2(aR[2].x, aR[2].y); u1.y = pack2(aR[2].z, aR[2].w);
        u1.z = pack2(aR[3].x, aR[3].y); u1.w = pack2(aR[3].z, aR[3].w);
        *(uint4*)dst = u0;
        *(uint4*)(dst + 16) = u1;
    };
    auto ldgB = [&](const __half* w, int KT, int c) {
        const uint4* p = (const uint4*)((const char*)(w + (size_t)(t >> 1) * KT)
                                        + c * 64 + (t & 1) * 32);
        bU[0] = p[0]; bU[1] = p[1];
    };
    auto stsB = [&](int slot) {
        char* dst = smem + SM_B0 + slot * ABUF + (t >> 1) * ARS + (t & 1) * 32;
        *(uint4*)dst = bU[0];
        *(uint4*)(dst + 16) = bU[1];
    };

    // k32-chunk compute: A m32 tile (2 LDSM.x4/kstep), B n64 (4 LDSM.x4/kstep), 16 HMMA/kstep
    auto compute = [&](uint32_t abase, uint32_t astep16, uint32_t bbase) {
#pragma unroll
        for (int ks = 0; ks < 2; ++ks) {
            uint32_t a0f[4], a1f[4];
            ldsm4(a0f, abase + ks * 32);
            ldsm4(a1f, abase + astep16 + ks * 32);
#pragma unroll
            for (int p = 0; p < 4; ++p) {
                uint32_t bf[4];
                ldsm4(bf, bbase + p * (16 * ARS) + ks * 32);
                mma16(acc[0][2 * p],     a0f, bf + 0);
                mma16(acc[0][2 * p + 1], a0f, bf + 2);
                mma16(acc[1][2 * p],     a1f, bf + 0);
                mma16(acc[1][2 * p + 1], a1f, bf + 2);
            }
        }
    };

    // ---------------- GEMM1: cat[128 x NSEG*128] @ w1 ----------------
    const int NC1 = NSEG * 4;
    ldgA(0); ldgB(wt1, KT1, 0);
    stsA(0); stsB(0);
    __syncthreads();

    for (int c = 0; c < NC1; ++c) {
        const bool pf = (c + 1 < NC1);
        if (pf) { ldgA(c + 1); ldgB(wt1, KT1, c + 1); }
        compute(sbase + SM_A0 + (c & 1) * ABUF + a_geo, 16 * ARS,
                sbase + SM_B0 + (c & 1) * ABUF + b_geo);
        if (pf) { stsA((c + 1) & 1); stsB((c + 1) & 1); }
        __syncthreads();
    }

    // prefetch first w2 chunk while doing epilogue1
    ldgB(wt2, 128, 0);

    // epilogue1: bias + SiLU -> half into Hs (row-major [row][128 halves])
    {
        float2 b1r[8];
#pragma unroll
        for (int jt = 0; jt < 8; ++jt) b1r[jt] = *(const float2*)(b1 + cb0 + jt * 8);
#pragma unroll
        for (int mt = 0; mt < 2; ++mt) {
            const int r0 = rm + mt * 16 + g;
#pragma unroll
            for (int jt = 0; jt < 8; ++jt) {
                const int cb = cb0 + jt * 8;
                float h0 = silu_f(acc[mt][jt][0] + b1r[jt].x);
                float h1 = silu_f(acc[mt][jt][1] + b1r[jt].y);
                float h2 = silu_f(acc[mt][jt][2] + b1r[jt].x);
                float h3 = silu_f(acc[mt][jt][3] + b1r[jt].y);
                *(uint32_t*)(smem + SM_HS + r0 * HRS + cb * 2)       = pack2(h0, h1);
                *(uint32_t*)(smem + SM_HS + (r0 + 8) * HRS + cb * 2) = pack2(h2, h3);
            }
        }
    }
#pragma unroll
    for (int mt = 0; mt < 2; ++mt)
#pragma unroll
        for (int jt = 0; jt < 8; ++jt)
#pragma unroll
            for (int q = 0; q < 4; ++q) acc[mt][jt][q] = 0.f;

    stsB(0);
    __syncthreads();

    // ---------------- GEMM2: h[128x128] @ w2 (A LDSM'd from Hs) ----------------
    for (int c = 0; c < 4; ++c) {
        const bool pf = (c + 1 < 4);
        if (pf) ldgB(wt2, 128, c + 1);
        compute(sbase + SM_HS + h_geo + c * 64, 16 * HRS,
                sbase + SM_B0 + (c & 1) * ABUF + b_geo);
        if (pf) stsB((c + 1) & 1);
        __syncthreads();
    }

    // ---------------- epilogue2: bias + register LayerNorm + out/scatter ----------------
    {
        float2 b2r[8], gmr[8], btr[8];
#pragma unroll
        for (int jt = 0; jt < 8; ++jt) {
            b2r[jt] = *(const float2*)(b2 + cb0 + jt * 8);
            gmr[jt] = *(const float2*)(gam + cb0 + jt * 8);
            btr[jt] = *(const float2*)(bet + cb0 + jt * 8);
        }
        // partial row sums over this thread's 16 cols per row
        float s[2][2] = {{0.f, 0.f}, {0.f, 0.f}};
        float ss[2][2] = {{0.f, 0.f}, {0.f, 0.f}};
#pragma unroll
        for (int mt = 0; mt < 2; ++mt)
#pragma unroll
            for (int jt = 0; jt < 8; ++jt) {
                float v0 = acc[mt][jt][0] + b2r[jt].x;
                float v1 = acc[mt][jt][1] + b2r[jt].y;
                float v2 = acc[mt][jt][2] + b2r[jt].x;
                float v3 = acc[mt][jt][3] + b2r[jt].y;
                s[mt][0] += v0 + v1;  ss[mt][0] += v0 * v0 + v1 * v1;
                s[mt][1] += v2 + v3;  ss[mt][1] += v2 * v2 + v3 * v3;
            }
#pragma unroll
        for (int off = 1; off <= 2; off <<= 1)
#pragma unroll
            for (int mt = 0; mt < 2; ++mt)
#pragma unroll
                for (int h = 0; h < 2; ++h) {
                    s[mt][h]  += __shfl_xor_sync(0xffffffffu, s[mt][h], off);
                    ss[mt][h] += __shfl_xor_sync(0xffffffffu, ss[mt][h], off);
                }
        float2* part = (float2*)smem;
        if (c4 == 0) {
#pragma unroll
            for (int mt = 0; mt < 2; ++mt)
#pragma unroll
                for (int h = 0; h < 2; ++h)
                    part[wn * 128 + rm + mt * 16 + g + h * 8] = make_float2(s[mt][h], ss[mt][h]);
        }
        __syncthreads();
#pragma unroll
        for (int mt = 0; mt < 2; ++mt)
#pragma unroll
            for (int h = 0; h < 2; ++h) {
                const int R = rm + mt * 16 + g + h * 8;
                const int m = m0 + R;
                float2 pa = part[R], pb = part[128 + R];
                float mu  = (pa.x + pb.x) * (1.0f / 128.0f);
                float var = (pa.y + pb.y) * (1.0f / 128.0f) - mu * mu;
                float rs  = rsqrtf(var + LNEPS);
                if (m < M) {
                    if (MODE == 0) {
                        float* base = g_agg + (size_t)scat[m] * D;
#pragma unroll
                        for (int jt = 0; jt < 8; ++jt) {
                            float v0 = acc[mt][jt][2 * h]     + b2r[jt].x;
                            float v1 = acc[mt][jt][2 * h + 1] + b2r[jt].y;
                            float o0 = (v0 - mu) * rs * gmr[jt].x + btr[jt].x;
                            float o1 = (v1 - mu) * rs * gmr[jt].y + btr[jt].y;
                            atomicAdd(base + cb0 + jt * 8,     o0);
                            atomicAdd(base + cb0 + jt * 8 + 1, o1);
                        }
                    } else {
                        const float* rv = resid + (size_t)m * D;
                        float* op = outp + (size_t)m * D;
#pragma unroll
                        for (int jt = 0; jt < 8; ++jt) {
                            float v0 = acc[mt][jt][2 * h]     + b2r[jt].x;
                            float v1 = acc[mt][jt][2 * h + 1] + b2r[jt].y;
                            float o0 = (v0 - mu) * rs * gmr[jt].x + btr[jt].x;
                            float o1 = (v1 - mu) * rs * gmr[jt].y + btr[jt].y;
                            float2 rr = *(const float2*)(rv + cb0 + jt * 8);
                            *(float2*)(op + cb0 + jt * 8) = make_float2(o0 + rr.x, o1 + rr.y);
                        }
                    }
                }
            }
    }
}

extern "C" void kernel_launch(void* const* d_in, const int* in_sizes, int n_in,
                              void* d_out, int out_size) {
    const float* g2m  = (const float*)d_in[0];
    const float* grid = (const float*)d_in[1];
    const float* mesh = (const float*)d_in[2];
    const int*   src  = (const int*)d_in[3];
    const int*   dst  = (const int*)d_in[4];
    const float* ew1 = (const float*)d_in[5];
    const float* eb1 = (const float*)d_in[6];
    const float* ew2 = (const float*)d_in[7];
    const float* eb2 = (const float*)d_in[8];
    const float* eg  = (const float*)d_in[9];
    const float* ebt = (const float*)d_in[10];
    const float* sw1 = (const float*)d_in[11];
    const float* sb1 = (const float*)d_in[12];
    const float* sw2 = (const float*)d_in[13];
    const float* sb2 = (const float*)d_in[14];
    const float* sg  = (const float*)d_in[15];
    const float* sbt = (const float*)d_in[16];
    const float* dw1 = (const float*)d_in[17];
    const float* db1 = (const float*)d_in[18];
    const float* dw2 = (const float*)d_in[19];
    const float* db2 = (const float*)d_in[20];
    const float* dg  = (const float*)d_in[21];
    const float* dbt = (const float*)d_in[22];

    float* grid_out = (float*)d_out;                  // [NGRID, D]
    float* mesh_out = grid_out + (size_t)NGRID * D;   // [NMESH, D]

    cudaFuncSetAttribute(mlp_kernel<3,0>, cudaFuncAttributeMaxDynamicSharedMemorySize, SM_TOTAL);
    cudaFuncSetAttribute(mlp_kernel<2,1>, cudaFuncAttributeMaxDynamicSharedMemorySize, SM_TOTAL);
    cudaFuncSetAttribute(mlp_kernel<1,2>, cudaFuncAttributeMaxDynamicSharedMemorySize, SM_TOTAL);

    zero_agg_kernel<<<(NMESH * D / 4 + 255) / 256, 256>>>();
    prep_kernel<<<(WT_TOTAL + 255) / 256, 256>>>(ew1, ew2, sw1, sw2, dw1, dw2);

    mlp_kernel<3,0><<<(NE + 127) / 128, 256, SM_TOTAL>>>(
        g2m, grid, mesh, src, dst, NE, WT_E1, WT_E2,
        eb1, eb2, eg, ebt, nullptr, nullptr, dst);

    mlp_kernel<1,2><<<(NGRID + 127) / 128, 256, SM_TOTAL>>>(
        grid, nullptr, nullptr, nullptr, nullptr, NGRID, WT_S1, WT_S2,
        sb1, sb2, sg, sbt, grid, grid_out, nullptr);

    mlp_kernel<2,1><<<(NMESH + 127) / 128, 256, SM_TOTAL>>>(
        nullptr, mesh, nullptr, nullptr, nullptr, NMESH, WT_D1, WT_D2,
        db1, db2, dg, dbt, mesh, mesh_out, nullptr);
}

// round 10
// speedup vs baseline: 5.7522x; 1.0477x over previous
#include <cuda_runtime.h>
#include <cuda_fp16.h>
#include <cstdint>

#define D 128
#define NE 500000
#define NGRID 200000
#define NMESH 40000
#define LNEPS 1e-5f

// smem byte layout
#define SM_A0   4096                  // A: 2 slots x (128 rows x 80 B)
#define ABUF    10240
#define ARS     80
#define SM_HS   24576                 // h: 128 rows x 272 B
#define HRS     272
#define SM_TOTAL 59392

// g_fragB word offsets (uint32): B in mma-fragment order per weight
#define FE1 0        // K=384 -> 24576 words
#define FE2 24576
#define FS1 32768
#define FS2 40960
#define FD1 49152
#define FD2 65536
#define FTOT 73728

__device__ __align__(16) float    g_agg[(size_t)NMESH * D];
__device__ __align__(16) uint32_t g_fragB[FTOT];
__device__ __align__(16) __half   grid_h[(size_t)NGRID * D];
__device__ __align__(16) __half   mesh_h[(size_t)NMESH * D];

__device__ __forceinline__ float silu_f(float x) { return x / (1.0f + __expf(-x)); }
__device__ __forceinline__ uint32_t pack2(float x, float y) {
    __half2 h = __floats2half2_rn(x, y);
    return *reinterpret_cast<uint32_t*>(&h);
}
__device__ __forceinline__ void mma16(float* c, const uint32_t* a, const uint32_t* b) {
    asm volatile(
        "mma.sync.aligned.m16n8k16.row.col.f32.f16.f16.f32 "
        "{%0,%1,%2,%3}, {%4,%5,%6,%7}, {%8,%9}, {%0,%1,%2,%3};"
        : "+f"(c[0]), "+f"(c[1]), "+f"(c[2]), "+f"(c[3])
        : "r"(a[0]), "r"(a[1]), "r"(a[2]), "r"(a[3]), "r"(b[0]), "r"(b[1]));
}
__device__ __forceinline__ void ldsm4(uint32_t* r, uint32_t saddr) {
    asm volatile("ldmatrix.sync.aligned.m8n8.x4.shared.b16 {%0,%1,%2,%3}, [%4];"
                 : "=r"(r[0]), "=r"(r[1]), "=r"(r[2]), "=r"(r[3]) : "r"(saddr));
}

__global__ void zero_agg_kernel() {
    size_t i = (size_t)blockIdx.x * blockDim.x + threadIdx.x;
    if (i < (size_t)NMESH * D / 4)
        ((float4*)g_agg)[i] = make_float4(0.f, 0.f, 0.f, 0.f);
}

__global__ void conv_grid_kernel(const float* __restrict__ s) {
    int i = blockIdx.x * blockDim.x + threadIdx.x;
    if (i < NGRID * D / 4) {
        float4 v = ((const float4*)s)[i];
        uint2 o;
        o.x = pack2(v.x, v.y);
        o.y = pack2(v.z, v.w);
        ((uint2*)grid_h)[i] = o;
    }
}
__global__ void conv_mesh_kernel(const float* __restrict__ s) {
    int i = blockIdx.x * blockDim.x + threadIdx.x;
    if (i < NMESH * D / 4) {
        float4 v = ((const float4*)s)[i];
        uint2 o;
        o.x = pack2(v.x, v.y);
        o.y = pack2(v.z, v.w);
        ((uint2*)mesh_h)[i] = o;
    }
}

// Pre-swizzle weights into mma-B-fragment order:
// word (c16*16+nt)*64 + lane*2 + j packs halves (w[k0][n], w[k0+1][n])
// with n = nt*8 + lane/4, k0 = c16*16 + j*8 + 2*(lane%4)
__global__ void prep_fragB(const float* __restrict__ ew1, const float* __restrict__ ew2,
                           const float* __restrict__ sw1, const float* __restrict__ sw2,
                           const float* __restrict__ dw1, const float* __restrict__ dw2) {
    int i = blockIdx.x * blockDim.x + threadIdx.x;
    if (i >= FTOT) return;
    const float* src; int off;
    if (i < FE2)      { src = ew1; off = FE1; }
    else if (i < FS1) { src = ew2; off = FE2; }
    else if (i < FS2) { src = sw1; off = FS1; }
    else if (i < FD1) { src = sw2; off = FS2; }
    else if (i < FD2) { src = dw1; off = FD1; }
    else              { src = dw2; off = FD2; }
    int j = i - off;
    int blk = j >> 6, r = j & 63;
    int ln = r >> 1, jw = r & 1;
    int c16 = blk >> 4, nt = blk & 15;
    int n  = nt * 8 + (ln >> 2);
    int k0 = c16 * 16 + jw * 8 + 2 * (ln & 3);
    g_fragB[i] = pack2(src[(size_t)k0 * 128 + n], src[(size_t)(k0 + 1) * 128 + n]);
}

// Fused MLP, fp16 mma m16n8k16, fp32 accum, register LayerNorm.
// B operands read directly from global in fragment order (no smem round-trip).
// NF = # leading fp32 segments; remaining segments come from half tables.
// MODE: 0 = edge (scatter-add), 1 = mesh (seg0=g_agg, residual), 2 = grid (residual)
template<int NSEG, int NF, int MODE>
__global__ __launch_bounds__(256, 2)
void mlp_kernel(const float* __restrict__ segF,
                const int* __restrict__ idx1, const int* __restrict__ idx2,
                int M, int wt1_off, int wt2_off,
                const float* __restrict__ b1, const float* __restrict__ b2,
                const float* __restrict__ gam, const float* __restrict__ bet,
                const float* __restrict__ resid, float* __restrict__ outp,
                const int* __restrict__ scat)
{
    extern __shared__ char smem[];
    const uint32_t sbase = (uint32_t)__cvta_generic_to_shared(smem);

    const int t    = threadIdx.x;
    const int lane = t & 31;
    const int warp = t >> 5;
    const int wm   = warp & 3;
    const int wn   = warp >> 2;
    const int m0   = blockIdx.x * 128;
    const int rm   = wm * 32;
    const int g    = lane >> 2;
    const int c4   = lane & 3;
    const int cb0  = wn * 64 + 2 * c4;

    const uint32_t a_geo = (uint32_t)((rm + (lane & 15)) * ARS + (lane >> 4) * 16);
    const uint32_t h_geo = (uint32_t)((rm + (lane & 15)) * HRS + (lane >> 4) * 16);

    const int ma = min(m0 + (t >> 1), M - 1);
    const float* sF = (MODE == 1) ? (const float*)g_agg : segF;
    const float* rpF = (NF > 0) ? sF + (size_t)ma * D : nullptr;
    const __half* hA = (MODE == 1) ? mesh_h : grid_h;
    const int iH0 = (MODE == 0) ? idx1[ma] : ma;
    const __half* rpH0 = hA + (size_t)iH0 * D;
    const __half* rpH1 = (NSEG == 3) ? mesh_h + (size_t)idx2[ma] * D : nullptr;

    const uint2* w1f = (const uint2*)(g_fragB + wt1_off);
    const uint2* w2f = (const uint2*)(g_fragB + wt2_off);

    float acc[2][8][4];
#pragma unroll
    for (int mt = 0; mt < 2; ++mt)
#pragma unroll
        for (int jt = 0; jt < 8; ++jt)
#pragma unroll
            for (int q = 0; q < 4; ++q) acc[mt][jt][q] = 0.f;

    float4 fR[4];
    uint4  hU[2];
    auto ldF = [&](int c) {
        const float4* p = (const float4*)(rpF + (c & 3) * 32 + (t & 1) * 16);
        fR[0] = p[0]; fR[1] = p[1]; fR[2] = p[2]; fR[3] = p[3];
    };
    auto stF = [&](int slot) {
        char* dst = smem + SM_A0 + slot * ABUF + (t >> 1) * ARS + (t & 1) * 32;
        uint4 u0, u1;
        u0.x = pack2(fR[0].x, fR[0].y); u0.y = pack2(fR[0].z, fR[0].w);
        u0.z = pack2(fR[1].x, fR[1].y); u0.w = pack2(fR[1].z, fR[1].w);
        u1.x = pack2(fR[2].x, fR[2].y); u1.y = pack2(fR[2].z, fR[2].w);
        u1.z = pack2(fR[3].x, fR[3].y); u1.w = pack2(fR[3].z, fR[3].w);
        *(uint4*)dst = u0;
        *(uint4*)(dst + 16) = u1;
    };
    auto ldH = [&](int c) {
        const __half* src = ((c >> 2) == NF) ? rpH0 : rpH1;
        const uint4* p = (const uint4*)((const char*)src + (c & 3) * 64 + (t & 1) * 32);
        hU[0] = p[0]; hU[1] = p[1];
    };
    auto stH = [&](int slot) {
        char* dst = smem + SM_A0 + slot * ABUF + (t >> 1) * ARS + (t & 1) * 32;
        *(uint4*)dst = hU[0];
        *(uint4*)(dst + 16) = hU[1];
    };

    auto compute = [&](uint32_t abase, uint32_t astep, const uint2* __restrict__ bw, int c) {
#pragma unroll
        for (int ks = 0; ks < 2; ++ks) {
            uint32_t a0f[4], a1f[4];
            ldsm4(a0f, abase + ks * 32);
            ldsm4(a1f, abase + astep + ks * 32);
            const uint2* bt = bw + ((((2 * c + ks) * 16) + wn * 8) << 5) + lane;
#pragma unroll
            for (int p = 0; p < 4; ++p) {
                uint2 B0 = bt[(2 * p) << 5];
                uint2 B1 = bt[(2 * p + 1) << 5];
                mma16(acc[0][2 * p],     a0f, &B0.x);
                mma16(acc[0][2 * p + 1], a0f, &B1.x);
                mma16(acc[1][2 * p],     a1f, &B0.x);
                mma16(acc[1][2 * p + 1], a1f, &B1.x);
            }
        }
    };

    // ---------------- GEMM1: cat[128 x NSEG*128] @ w1 ----------------
    const int NC1 = NSEG * 4;
    if (NF > 0) { ldF(0); stF(0); }
    else        { ldH(0); stH(0); }
    __syncthreads();

    for (int c = 0; c < NC1; ++c) {
        const bool pf  = (c + 1 < NC1);
        const bool nxF = (NF > 0) && (((c + 1) >> 2) < NF);
        if (pf) { if (nxF) ldF(c + 1); else ldH(c + 1); }
        compute(sbase + SM_A0 + (c & 1) * ABUF + a_geo, 16 * ARS, w1f, c);
        if (pf) { if (nxF) stF((c + 1) & 1); else stH((c + 1) & 1); }
        __syncthreads();
    }

    // epilogue1: bias + SiLU -> half h into Hs (row-major)
    {
        float2 b1r[8];
#pragma unroll
        for (int jt = 0; jt < 8; ++jt) b1r[jt] = *(const float2*)(b1 + cb0 + jt * 8);
#pragma unroll
        for (int mt = 0; mt < 2; ++mt) {
            const int r0 = rm + mt * 16 + g;
#pragma unroll
            for (int jt = 0; jt < 8; ++jt) {
                const int cb = cb0 + jt * 8;
                float h0 = silu_f(acc[mt][jt][0] + b1r[jt].x);
                float h1 = silu_f(acc[mt][jt][1] + b1r[jt].y);
                float h2 = silu_f(acc[mt][jt][2] + b1r[jt].x);
                float h3 = silu_f(acc[mt][jt][3] + b1r[jt].y);
                *(uint32_t*)(smem + SM_HS + r0 * HRS + cb * 2)       = pack2(h0, h1);
                *(uint32_t*)(smem + SM_HS + (r0 + 8) * HRS + cb * 2) = pack2(h2, h3);
            }
        }
    }
#pragma unroll
    for (int mt = 0; mt < 2; ++mt)
#pragma unroll
        for (int jt = 0; jt < 8; ++jt)
#pragma unroll
            for (int q = 0; q < 4; ++q) acc[mt][jt][q] = 0.f;
    __syncthreads();

    // ---------------- GEMM2: h[128x128] @ w2 — no barriers, B from global ----------------
#pragma unroll
    for (int c = 0; c < 4; ++c)
        compute(sbase + SM_HS + h_geo + c * 64, 16 * HRS, w2f, c);

    // ---------------- epilogue2: bias + register LayerNorm + out/scatter ----------------
    {
        float2 b2r[8], gmr[8], btr[8];
#pragma unroll
        for (int jt = 0; jt < 8; ++jt) {
            b2r[jt] = *(const float2*)(b2 + cb0 + jt * 8);
            gmr[jt] = *(const float2*)(gam + cb0 + jt * 8);
            btr[jt] = *(const float2*)(bet + cb0 + jt * 8);
        }
        float s[2][2]  = {{0.f, 0.f}, {0.f, 0.f}};
        float ss[2][2] = {{0.f, 0.f}, {0.f, 0.f}};
#pragma unroll
        for (int mt = 0; mt < 2; ++mt)
#pragma unroll
            for (int jt = 0; jt < 8; ++jt) {
                float v0 = acc[mt][jt][0] + b2r[jt].x;
                float v1 = acc[mt][jt][1] + b2r[jt].y;
                float v2 = acc[mt][jt][2] + b2r[jt].x;
                float v3 = acc[mt][jt][3] + b2r[jt].y;
                s[mt][0] += v0 + v1;  ss[mt][0] += v0 * v0 + v1 * v1;
                s[mt][1] += v2 + v3;  ss[mt][1] += v2 * v2 + v3 * v3;
            }
#pragma unroll
        for (int off = 1; off <= 2; off <<= 1)
#pragma unroll
            for (int mt = 0; mt < 2; ++mt)
#pragma unroll
                for (int h = 0; h < 2; ++h) {
                    s[mt][h]  += __shfl_xor_sync(0xffffffffu, s[mt][h], off);
                    ss[mt][h] += __shfl_xor_sync(0xffffffffu, ss[mt][h], off);
                }
        float2* part = (float2*)smem;
        if (c4 == 0) {
#pragma unroll
            for (int mt = 0; mt < 2; ++mt)
#pragma unroll
                for (int h = 0; h < 2; ++h)
                    part[wn * 128 + rm + mt * 16 + g + h * 8] = make_float2(s[mt][h], ss[mt][h]);
        }
        __syncthreads();
#pragma unroll
        for (int mt = 0; mt < 2; ++mt)
#pragma unroll
            for (int h = 0; h < 2; ++h) {
                const int R = rm + mt * 16 + g + h * 8;
                const int m = m0 + R;
                float2 pa = part[R], pb = part[128 + R];
                float mu  = (pa.x + pb.x) * (1.0f / 128.0f);
                float var = (pa.y + pb.y) * (1.0f / 128.0f) - mu * mu;
                float rs  = rsqrtf(var + LNEPS);
                if (m < M) {
                    if (MODE == 0) {
                        float* base = g_agg + (size_t)scat[m] * D;
#pragma unroll
                        for (int jt = 0; jt < 8; ++jt) {
                            float v0 = acc[mt][jt][2 * h]     + b2r[jt].x;
                            float v1 = acc[mt][jt][2 * h + 1] + b2r[jt].y;
                            float o0 = (v0 - mu) * rs * gmr[jt].x + btr[jt].x;
                            float o1 = (v1 - mu) * rs * gmr[jt].y + btr[jt].y;
                            atomicAdd((float2*)(base + cb0 + jt * 8), make_float2(o0, o1));
                        }
                    } else {
                        const float* rv = resid + (size_t)m * D;
                        float* op = outp + (size_t)m * D;
#pragma unroll
                        for (int jt = 0; jt < 8; ++jt) {
                            float v0 = acc[mt][jt][2 * h]     + b2r[jt].x;
                            float v1 = acc[mt][jt][2 * h + 1] + b2r[jt].y;
                            float o0 = (v0 - mu) * rs * gmr[jt].x + btr[jt].x;
                            float o1 = (v1 - mu) * rs * gmr[jt].y + btr[jt].y;
                            float2 rr = *(const float2*)(rv + cb0 + jt * 8);
                            *(float2*)(op + cb0 + jt * 8) = make_float2(o0 + rr.x, o1 + rr.y);
                        }
                    }
                }
            }
    }
}

extern "C" void kernel_launch(void* const* d_in, const int* in_sizes, int n_in,
                              void* d_out, int out_size) {
    const float* g2m  = (const float*)d_in[0];
    const float* grid = (const float*)d_in[1];
    const float* mesh = (const float*)d_in[2];
    const int*   src  = (const int*)d_in[3];
    const int*   dst  = (const int*)d_in[4];
    const float* ew1 = (const float*)d_in[5];
    const float* eb1 = (const float*)d_in[6];
    const float* ew2 = (const float*)d_in[7];
    const float* eb2 = (const float*)d_in[8];
    const float* eg  = (const float*)d_in[9];
    const float* ebt = (const float*)d_in[10];
    const float* sw1 = (const float*)d_in[11];
    const float* sb1 = (const float*)d_in[12];
    const float* sw2 = (const float*)d_in[13];
    const float* sb2 = (const float*)d_in[14];
    const float* sg  = (const float*)d_in[15];
    const float* sbt = (const float*)d_in[16];
    const float* dw1 = (const float*)d_in[17];
    const float* db1 = (const float*)d_in[18];
    const float* dw2 = (const float*)d_in[19];
    const float* db2 = (const float*)d_in[20];
    const float* dg  = (const float*)d_in[21];
    const float* dbt = (const float*)d_in[22];

    float* grid_out = (float*)d_out;                  // [NGRID, D]
    float* mesh_out = grid_out + (size_t)NGRID * D;   // [NMESH, D]

    cudaFuncSetAttribute(mlp_kernel<3,1,0>, cudaFuncAttributeMaxDynamicSharedMemorySize, SM_TOTAL);
    cudaFuncSetAttribute(mlp_kernel<2,1,1>, cudaFuncAttributeMaxDynamicSharedMemorySize, SM_TOTAL);
    cudaFuncSetAttribute(mlp_kernel<1,0,2>, cudaFuncAttributeMaxDynamicSharedMemorySize, SM_TOTAL);

    zero_agg_kernel<<<(NMESH * D / 4 + 255) / 256, 256>>>();
    conv_grid_kernel<<<(NGRID * D / 4 + 255) / 256, 256>>>(grid);
    conv_mesh_kernel<<<(NMESH * D / 4 + 255) / 256, 256>>>(mesh);
    prep_fragB<<<(FTOT + 255) / 256, 256>>>(ew1, ew2, sw1, sw2, dw1, dw2);

    mlp_kernel<3,1,0><<<(NE + 127) / 128, 256, SM_TOTAL>>>(
        g2m, src, dst, NE, FE1, FE2,
        eb1, eb2, eg, ebt, nullptr, nullptr, dst);

    mlp_kernel<1,0,2><<<(NGRID + 127) / 128, 256, SM_TOTAL>>>(
        nullptr, nullptr, nullptr, NGRID, FS1, FS2,
        sb1, sb2, sg, sbt, grid, grid_out, nullptr);

    mlp_kernel<2,1,1><<<(NMESH + 127) / 128, 256, SM_TOTAL>>>(
        nullptr, nullptr, nullptr, NMESH, FD1, FD2,
        db1, db2, dg, dbt, mesh, mesh_out, nullptr);
}

// round 11
// speedup vs baseline: 5.9862x; 1.0407x over previous
#include <cuda_runtime.h>
#include <cuda_fp16.h>
#include <cstdint>

#define D 128
#define NE 500000
#define NGRID 200000
#define NMESH 40000
#define LNEPS 1e-5f

#define NB_EDGE 3907
#define NB_GRID 1563
#define NB_MESH 313

// smem byte layout
#define SM_A0   4096
#define ABUF    10240
#define ARS     80
#define SM_HS   24576
#define HRS     272
#define SM_TOTAL 59392

// g_fragB word offsets (uint32): B in mma-fragment order per weight
#define FE1 0
#define FE2 24576
#define FS1 32768
#define FS2 40960
#define FD1 49152
#define FD2 65536
#define FTOT 73728

// setup kernel block ranges
#define SB_CG 25000            // conv grid: 6.4M words /256
#define SB_CM (SB_CG + 5000)   // conv mesh
#define SB_ZA (SB_CM + 5000)   // zero agg
#define SB_PF (SB_ZA + 288)    // prep fragB
#define SB_TOT SB_PF

__device__ __align__(16) float    g_agg[(size_t)NMESH * D];
__device__ __align__(16) uint32_t g_fragB[FTOT];
__device__ __align__(16) __half   grid_h[(size_t)NGRID * D];
__device__ __align__(16) __half   mesh_h[(size_t)NMESH * D];

__device__ __forceinline__ float silu_f(float x) { return x / (1.0f + __expf(-x)); }
__device__ __forceinline__ uint32_t pack2(float x, float y) {
    __half2 h = __floats2half2_rn(x, y);
    return *reinterpret_cast<uint32_t*>(&h);
}
__device__ __forceinline__ void mma16(float* c, const uint32_t* a, const uint32_t* b) {
    asm volatile(
        "mma.sync.aligned.m16n8k16.row.col.f32.f16.f16.f32 "
        "{%0,%1,%2,%3}, {%4,%5,%6,%7}, {%8,%9}, {%0,%1,%2,%3};"
        : "+f"(c[0]), "+f"(c[1]), "+f"(c[2]), "+f"(c[3])
        : "r"(a[0]), "r"(a[1]), "r"(a[2]), "r"(a[3]), "r"(b[0]), "r"(b[1]));
}
__device__ __forceinline__ void ldsm4(uint32_t* r, uint32_t saddr) {
    asm volatile("ldmatrix.sync.aligned.m8n8.x4.shared.b16 {%0,%1,%2,%3}, [%4];"
                 : "=r"(r[0]), "=r"(r[1]), "=r"(r[2]), "=r"(r[3]) : "r"(saddr));
}

// ---------------- fused setup: conv grid/mesh, zero agg, pre-swizzle weights ----------------
__global__ void setup_kernel(const float* __restrict__ grid, const float* __restrict__ mesh,
                             const float* __restrict__ ew1, const float* __restrict__ ew2,
                             const float* __restrict__ sw1, const float* __restrict__ sw2,
                             const float* __restrict__ dw1, const float* __restrict__ dw2) {
    const int b = blockIdx.x;
    const int t = threadIdx.x;
    if (b < SB_CG) {
        int i = b * 256 + t;
        float4 v = ((const float4*)grid)[i];
        uint2 o; o.x = pack2(v.x, v.y); o.y = pack2(v.z, v.w);
        ((uint2*)grid_h)[i] = o;
    } else if (b < SB_CM) {
        int i = (b - SB_CG) * 256 + t;
        float4 v = ((const float4*)mesh)[i];
        uint2 o; o.x = pack2(v.x, v.y); o.y = pack2(v.z, v.w);
        ((uint2*)mesh_h)[i] = o;
    } else if (b < SB_ZA) {
        int i = (b - SB_CM) * 256 + t;
        ((float4*)g_agg)[i] = make_float4(0.f, 0.f, 0.f, 0.f);
    } else {
        int i = (b - SB_ZA) * 256 + t;
        if (i >= FTOT) return;
        const float* src; int off;
        if (i < FE2)      { src = ew1; off = FE1; }
        else if (i < FS1) { src = ew2; off = FE2; }
        else if (i < FS2) { src = sw1; off = FS1; }
        else if (i < FD1) { src = sw2; off = FS2; }
        else if (i < FD2) { src = dw1; off = FD1; }
        else              { src = dw2; off = FD2; }
        int j = i - off;
        int blk = j >> 6, r = j & 63;
        int ln = r >> 1, jw = r & 1;
        int c16 = blk >> 4, nt = blk & 15;
        int n  = nt * 8 + (ln >> 2);
        int k0 = c16 * 16 + jw * 8 + 2 * (ln & 3);
        g_fragB[i] = pack2(src[(size_t)k0 * 128 + n], src[(size_t)(k0 + 1) * 128 + n]);
    }
}

// ---------------- fused MLP body (identical numerics to R10) ----------------
template<int NSEG, int NF, int MODE>
__device__ __forceinline__
void mlp_body(int bid, char* smem,
              const float* __restrict__ segF,
              const int* __restrict__ idx1, const int* __restrict__ idx2,
              int M, int wt1_off, int wt2_off,
              const float* __restrict__ b1, const float* __restrict__ b2,
              const float* __restrict__ gam, const float* __restrict__ bet,
              const float* __restrict__ resid, float* __restrict__ outp,
              const int* __restrict__ scat)
{
    const uint32_t sbase = (uint32_t)__cvta_generic_to_shared(smem);

    const int t    = threadIdx.x;
    const int lane = t & 31;
    const int warp = t >> 5;
    const int wm   = warp & 3;
    const int wn   = warp >> 2;
    const int m0   = bid * 128;
    const int rm   = wm * 32;
    const int g    = lane >> 2;
    const int c4   = lane & 3;
    const int cb0  = wn * 64 + 2 * c4;

    const uint32_t a_geo = (uint32_t)((rm + (lane & 15)) * ARS + (lane >> 4) * 16);
    const uint32_t h_geo = (uint32_t)((rm + (lane & 15)) * HRS + (lane >> 4) * 16);

    const int ma = min(m0 + (t >> 1), M - 1);
    const float* sF = (MODE == 1) ? (const float*)g_agg : segF;
    const float* rpF = (NF > 0) ? sF + (size_t)ma * D : nullptr;
    const __half* hA = (MODE == 1) ? mesh_h : grid_h;
    const int iH0 = (MODE == 0) ? idx1[ma] : ma;
    const __half* rpH0 = hA + (size_t)iH0 * D;
    const __half* rpH1 = (NSEG == 3) ? mesh_h + (size_t)idx2[ma] * D : nullptr;

    const uint2* w1f = (const uint2*)(g_fragB + wt1_off);
    const uint2* w2f = (const uint2*)(g_fragB + wt2_off);

    float acc[2][8][4];
#pragma unroll
    for (int mt = 0; mt < 2; ++mt)
#pragma unroll
        for (int jt = 0; jt < 8; ++jt)
#pragma unroll
            for (int q = 0; q < 4; ++q) acc[mt][jt][q] = 0.f;

    float4 fR[4];
    uint4  hU[2];
    auto ldF = [&](int c) {
        const float4* p = (const float4*)(rpF + (c & 3) * 32 + (t & 1) * 16);
        fR[0] = p[0]; fR[1] = p[1]; fR[2] = p[2]; fR[3] = p[3];
    };
    auto stF = [&](int slot) {
        char* dst = smem + SM_A0 + slot * ABUF + (t >> 1) * ARS + (t & 1) * 32;
        uint4 u0, u1;
        u0.x = pack2(fR[0].x, fR[0].y); u0.y = pack2(fR[0].z, fR[0].w);
        u0.z = pack2(fR[1].x, fR[1].y); u0.w = pack2(fR[1].z, fR[1].w);
        u1.x = pack2(fR[2].x, fR[2].y); u1.y = pack2(fR[2].z, fR[2].w);
        u1.z = pack2(fR[3].x, fR[3].y); u1.w = pack2(fR[3].z, fR[3].w);
        *(uint4*)dst = u0;
        *(uint4*)(dst + 16) = u1;
    };
    auto ldH = [&](int c) {
        const __half* src = ((c >> 2) == NF) ? rpH0 : rpH1;
        const uint4* p = (const uint4*)((const char*)src + (c & 3) * 64 + (t & 1) * 32);
        hU[0] = p[0]; hU[1] = p[1];
    };
    auto stH = [&](int slot) {
        char* dst = smem + SM_A0 + slot * ABUF + (t >> 1) * ARS + (t & 1) * 32;
        *(uint4*)dst = hU[0];
        *(uint4*)(dst + 16) = hU[1];
    };

    auto compute = [&](uint32_t abase, uint32_t astep, const uint2* __restrict__ bw, int c) {
#pragma unroll
        for (int ks = 0; ks < 2; ++ks) {
            uint32_t a0f[4], a1f[4];
            ldsm4(a0f, abase + ks * 32);
            ldsm4(a1f, abase + astep + ks * 32);
            const uint2* bt = bw + ((((2 * c + ks) * 16) + wn * 8) << 5) + lane;
#pragma unroll
            for (int p = 0; p < 4; ++p) {
                uint2 B0 = bt[(2 * p) << 5];
                uint2 B1 = bt[(2 * p + 1) << 5];
                mma16(acc[0][2 * p],     a0f, &B0.x);
                mma16(acc[0][2 * p + 1], a0f, &B1.x);
                mma16(acc[1][2 * p],     a1f, &B0.x);
                mma16(acc[1][2 * p + 1], a1f, &B1.x);
            }
        }
    };

    // ---------------- GEMM1 ----------------
    const int NC1 = NSEG * 4;
    if (NF > 0) { ldF(0); stF(0); }
    else        { ldH(0); stH(0); }
    __syncthreads();

    for (int c = 0; c < NC1; ++c) {
        const bool pf  = (c + 1 < NC1);
        const bool nxF = (NF > 0) && (((c + 1) >> 2) < NF);
        if (pf) { if (nxF) ldF(c + 1); else ldH(c + 1); }
        compute(sbase + SM_A0 + (c & 1) * ABUF + a_geo, 16 * ARS, w1f, c);
        if (pf) { if (nxF) stF((c + 1) & 1); else stH((c + 1) & 1); }
        __syncthreads();
    }

    // epilogue1: bias + SiLU -> half h into Hs
    {
        float2 b1r[8];
#pragma unroll
        for (int jt = 0; jt < 8; ++jt) b1r[jt] = *(const float2*)(b1 + cb0 + jt * 8);
#pragma unroll
        for (int mt = 0; mt < 2; ++mt) {
            const int r0 = rm + mt * 16 + g;
#pragma unroll
            for (int jt = 0; jt < 8; ++jt) {
                const int cb = cb0 + jt * 8;
                float h0 = silu_f(acc[mt][jt][0] + b1r[jt].x);
                float h1 = silu_f(acc[mt][jt][1] + b1r[jt].y);
                float h2 = silu_f(acc[mt][jt][2] + b1r[jt].x);
                float h3 = silu_f(acc[mt][jt][3] + b1r[jt].y);
                *(uint32_t*)(smem + SM_HS + r0 * HRS + cb * 2)       = pack2(h0, h1);
                *(uint32_t*)(smem + SM_HS + (r0 + 8) * HRS + cb * 2) = pack2(h2, h3);
            }
        }
    }
#pragma unroll
    for (int mt = 0; mt < 2; ++mt)
#pragma unroll
        for (int jt = 0; jt < 8; ++jt)
#pragma unroll
            for (int q = 0; q < 4; ++q) acc[mt][jt][q] = 0.f;
    __syncthreads();

    // ---------------- GEMM2 (no barriers, B from global) ----------------
#pragma unroll
    for (int c = 0; c < 4; ++c)
        compute(sbase + SM_HS + h_geo + c * 64, 16 * HRS, w2f, c);

    // ---------------- epilogue2: bias + register LN + out/scatter ----------------
    {
        float2 b2r[8], gmr[8], btr[8];
#pragma unroll
        for (int jt = 0; jt < 8; ++jt) {
            b2r[jt] = *(const float2*)(b2 + cb0 + jt * 8);
            gmr[jt] = *(const float2*)(gam + cb0 + jt * 8);
            btr[jt] = *(const float2*)(bet + cb0 + jt * 8);
        }
        float s[2][2]  = {{0.f, 0.f}, {0.f, 0.f}};
        float ss[2][2] = {{0.f, 0.f}, {0.f, 0.f}};
#pragma unroll
        for (int mt = 0; mt < 2; ++mt)
#pragma unroll
            for (int jt = 0; jt < 8; ++jt) {
                float v0 = acc[mt][jt][0] + b2r[jt].x;
                float v1 = acc[mt][jt][1] + b2r[jt].y;
                float v2 = acc[mt][jt][2] + b2r[jt].x;
                float v3 = acc[mt][jt][3] + b2r[jt].y;
                s[mt][0] += v0 + v1;  ss[mt][0] += v0 * v0 + v1 * v1;
                s[mt][1] += v2 + v3;  ss[mt][1] += v2 * v2 + v3 * v3;
            }
#pragma unroll
        for (int off = 1; off <= 2; off <<= 1)
#pragma unroll
            for (int mt = 0; mt < 2; ++mt)
#pragma unroll
                for (int h = 0; h < 2; ++h) {
                    s[mt][h]  += __shfl_xor_sync(0xffffffffu, s[mt][h], off);
                    ss[mt][h] += __shfl_xor_sync(0xffffffffu, ss[mt][h], off);
                }
        float2* part = (float2*)smem;
        if (c4 == 0) {
#pragma unroll
            for (int mt = 0; mt < 2; ++mt)
#pragma unroll
                for (int h = 0; h < 2; ++h)
                    part[wn * 128 + rm + mt * 16 + g + h * 8] = make_float2(s[mt][h], ss[mt][h]);
        }
        __syncthreads();
#pragma unroll
        for (int mt = 0; mt < 2; ++mt)
#pragma unroll
            for (int h = 0; h < 2; ++h) {
                const int R = rm + mt * 16 + g + h * 8;
                const int m = m0 + R;
                float2 pa = part[R], pb = part[128 + R];
                float mu  = (pa.x + pb.x) * (1.0f / 128.0f);
                float var = (pa.y + pb.y) * (1.0f / 128.0f) - mu * mu;
                float rs  = rsqrtf(var + LNEPS);
                if (m < M) {
                    if (MODE == 0) {
                        float* base = g_agg + (size_t)scat[m] * D;
#pragma unroll
                        for (int jt = 0; jt < 8; ++jt) {
                            float v0 = acc[mt][jt][2 * h]     + b2r[jt].x;
                            float v1 = acc[mt][jt][2 * h + 1] + b2r[jt].y;
                            float o0 = (v0 - mu) * rs * gmr[jt].x + btr[jt].x;
                            float o1 = (v1 - mu) * rs * gmr[jt].y + btr[jt].y;
                            atomicAdd((float2*)(base + cb0 + jt * 8), make_float2(o0, o1));
                        }
                    } else {
                        const float* rv = resid + (size_t)m * D;
                        float* op = outp + (size_t)m * D;
#pragma unroll
                        for (int jt = 0; jt < 8; ++jt) {
                            float v0 = acc[mt][jt][2 * h]     + b2r[jt].x;
                            float v1 = acc[mt][jt][2 * h + 1] + b2r[jt].y;
                            float o0 = (v0 - mu) * rs * gmr[jt].x + btr[jt].x;
                            float o1 = (v1 - mu) * rs * gmr[jt].y + btr[jt].y;
                            float2 rr = *(const float2*)(rv + cb0 + jt * 8);
                            *(float2*)(op + cb0 + jt * 8) = make_float2(o0 + rr.x, o1 + rr.y);
                        }
                    }
                }
            }
    }
}

// edge blocks [0, NB_EDGE), grid-node blocks [NB_EDGE, NB_EDGE+NB_GRID)
__global__ __launch_bounds__(256, 2)
void edge_grid_kernel(const float* __restrict__ g2m,
                      const int* __restrict__ src, const int* __restrict__ dst,
                      const float* __restrict__ eb1, const float* __restrict__ eb2,
                      const float* __restrict__ eg,  const float* __restrict__ ebt,
                      const float* __restrict__ sb1, const float* __restrict__ sb2,
                      const float* __restrict__ sg,  const float* __restrict__ sbt,
                      const float* __restrict__ gridf, float* __restrict__ grid_out)
{
    extern __shared__ char smem[];
    const int b = blockIdx.x;
    if (b < NB_EDGE) {
        mlp_body<3,1,0>(b, smem, g2m, src, dst, NE, FE1, FE2,
                        eb1, eb2, eg, ebt, nullptr, nullptr, dst);
    } else {
        mlp_body<1,0,2>(b - NB_EDGE, smem, nullptr, nullptr, nullptr, NGRID, FS1, FS2,
                        sb1, sb2, sg, sbt, gridf, grid_out, nullptr);
    }
}

__global__ __launch_bounds__(256, 2)
void mesh_kernel(const float* __restrict__ db1, const float* __restrict__ db2,
                 const float* __restrict__ dg,  const float* __restrict__ dbt,
                 const float* __restrict__ mesh, float* __restrict__ mesh_out)
{
    extern __shared__ char smem[];
    mlp_body<2,1,1>(blockIdx.x, smem, nullptr, nullptr, nullptr, NMESH, FD1, FD2,
                    db1, db2, dg, dbt, mesh, mesh_out, nullptr);
}

extern "C" void kernel_launch(void* const* d_in, const int* in_sizes, int n_in,
                              void* d_out, int out_size) {
    const float* g2m  = (const float*)d_in[0];
    const float* grid = (const float*)d_in[1];
    const float* mesh = (const float*)d_in[2];
    const int*   src  = (const int*)d_in[3];
    const int*   dst  = (const int*)d_in[4];
    const float* ew1 = (const float*)d_in[5];
    const float* eb1 = (const float*)d_in[6];
    const float* ew2 = (const float*)d_in[7];
    const float* eb2 = (const float*)d_in[8];
    const float* eg  = (const float*)d_in[9];
    const float* ebt = (const float*)d_in[10];
    const float* sw1 = (const float*)d_in[11];
    const float* sb1 = (const float*)d_in[12];
    const float* sw2 = (const float*)d_in[13];
    const float* sb2 = (const float*)d_in[14];
    const float* sg  = (const float*)d_in[15];
    const float* sbt = (const float*)d_in[16];
    const float* dw1 = (const float*)d_in[17];
    const float* db1 = (const float*)d_in[18];
    const float* dw2 = (const float*)d_in[19];
    const float* db2 = (const float*)d_in[20];
    const float* dg  = (const float*)d_in[21];
    const float* dbt = (const float*)d_in[22];

    float* grid_out = (float*)d_out;                  // [NGRID, D]
    float* mesh_out = grid_out + (size_t)NGRID * D;   // [NMESH, D]

    cudaFuncSetAttribute(edge_grid_kernel, cudaFuncAttributeMaxDynamicSharedMemorySize, SM_TOTAL);
    cudaFuncSetAttribute(mesh_kernel, cudaFuncAttributeMaxDynamicSharedMemorySize, SM_TOTAL);

    setup_kernel<<<SB_TOT, 256>>>(grid, mesh, ew1, ew2, sw1, sw2, dw1, dw2);

    edge_grid_kernel<<<NB_EDGE + NB_GRID, 256, SM_TOTAL>>>(
        g2m, src, dst, eb1, eb2, eg, ebt, sb1, sb2, sg, sbt, grid, grid_out);

    mesh_kernel<<<NB_MESH, 256, SM_TOTAL>>>(db1, db2, dg, dbt, mesh, mesh_out);
}